// round 1
// baseline (speedup 1.0000x reference)
#include <cuda_runtime.h>
#include <cuda_bf16.h>
#include <math.h>

// Problem constants
#define Tn   2048
#define Dn   2048
#define Hn   16
#define HDn  128
#define Ln   512
#define RDn  64
#define Kn   32
#define SCALE_ATTN (0.07216878364870323f)  // 1/sqrt(192)

// ---------------------------------------------------------------------------
// Scratch (static device globals -- no allocation allowed)
// ---------------------------------------------------------------------------
__device__ float g_ql [Tn * Ln];        // (T, L)
__device__ float g_ckv[Tn * Ln];        // (T, L)
__device__ float g_q  [Tn * Dn];        // (T, H*HD)
__device__ float g_qr [Tn * Hn * RDn];  // (T, H*RD)
__device__ float g_k  [Tn * Dn];        // (T, H*HD)
__device__ float g_v  [Tn * Dn];        // (T, H*HD)
__device__ float g_kr [Tn * RDn];       // (T, RD)
__device__ float g_ao [Tn * Dn];        // attention output (T, H*HD)

// ---------------------------------------------------------------------------
// SGEMM: C[M,N] = A[M,K] * B[K,N], row-major, fp32.
// BM=BN=128, BK=8, 256 threads, 8x8 per thread.
// Requires M%128==0, N%128==0, K%8==0.
// ---------------------------------------------------------------------------
#define BM 128
#define BN 128
#define BKK 8
#define TM 8
#define TN 8

__global__ __launch_bounds__(256, 2)
void sgemm_kernel(const float* __restrict__ A, const float* __restrict__ B,
                  float* __restrict__ C, int M, int N, int Kd)
{
    __shared__ float As[BKK][BM];
    __shared__ float Bs[BKK][BN];

    const int bx = blockIdx.x;   // along N
    const int by = blockIdx.y;   // along M
    const int tid = threadIdx.x;
    const int tx = tid & 15;     // along N (x8)
    const int ty = tid >> 4;     // along M (x8)

    const int aRow = tid >> 1;
    const int aCol = (tid & 1) * 4;
    const int bRow = tid >> 5;
    const int bCol = (tid & 31) * 4;

    const float* Aptr = A + (by * BM + aRow) * Kd + aCol;
    const float* Bptr = B + bRow * N + bx * BN + bCol;

    float acc[TM][TN];
#pragma unroll
    for (int i = 0; i < TM; i++)
#pragma unroll
        for (int j = 0; j < TN; j++) acc[i][j] = 0.f;

    for (int k0 = 0; k0 < Kd; k0 += BKK) {
        float4 av = *reinterpret_cast<const float4*>(Aptr + k0);
        As[aCol + 0][aRow] = av.x;
        As[aCol + 1][aRow] = av.y;
        As[aCol + 2][aRow] = av.z;
        As[aCol + 3][aRow] = av.w;
        *reinterpret_cast<float4*>(&Bs[bRow][bCol]) =
            *reinterpret_cast<const float4*>(Bptr + (size_t)k0 * N);
        __syncthreads();

#pragma unroll
        for (int kk = 0; kk < BKK; kk++) {
            float ar[TM], br[TN];
            float4 a0 = *reinterpret_cast<const float4*>(&As[kk][ty * TM]);
            float4 a1 = *reinterpret_cast<const float4*>(&As[kk][ty * TM + 4]);
            ar[0]=a0.x; ar[1]=a0.y; ar[2]=a0.z; ar[3]=a0.w;
            ar[4]=a1.x; ar[5]=a1.y; ar[6]=a1.z; ar[7]=a1.w;
            float4 b0 = *reinterpret_cast<const float4*>(&Bs[kk][tx * TN]);
            float4 b1 = *reinterpret_cast<const float4*>(&Bs[kk][tx * TN + 4]);
            br[0]=b0.x; br[1]=b0.y; br[2]=b0.z; br[3]=b0.w;
            br[4]=b1.x; br[5]=b1.y; br[6]=b1.z; br[7]=b1.w;
#pragma unroll
            for (int i = 0; i < TM; i++)
#pragma unroll
                for (int j = 0; j < TN; j++)
                    acc[i][j] = fmaf(ar[i], br[j], acc[i][j]);
        }
        __syncthreads();
    }

#pragma unroll
    for (int i = 0; i < TM; i++) {
        float* crow = C + (size_t)(by * BM + ty * TM + i) * N + bx * BN + tx * TN;
        float4 v0 = {acc[i][0], acc[i][1], acc[i][2], acc[i][3]};
        float4 v1 = {acc[i][4], acc[i][5], acc[i][6], acc[i][7]};
        *reinterpret_cast<float4*>(crow)     = v0;
        *reinterpret_cast<float4*>(crow + 4) = v1;
    }
}

// ---------------------------------------------------------------------------
// kr = rope(x @ Wkr): warp handles 8 rows, lane handles cols (lane, lane+32)
// ---------------------------------------------------------------------------
__global__ void kr_kernel(const float* __restrict__ x,
                          const float* __restrict__ Wkr,
                          float* __restrict__ krout)
{
    const int warp = (blockIdx.x * blockDim.x + threadIdx.x) >> 5;
    const int lane = threadIdx.x & 31;
    const int t0 = warp * 8;
    if (t0 >= Tn) return;

    float lo[8], hi[8];
#pragma unroll
    for (int i = 0; i < 8; i++) { lo[i] = 0.f; hi[i] = 0.f; }

    for (int k = 0; k < Dn; k++) {
        float blo = __ldg(&Wkr[k * RDn + lane]);
        float bhi = __ldg(&Wkr[k * RDn + lane + 32]);
#pragma unroll
        for (int i = 0; i < 8; i++) {
            float xv = __ldg(&x[(size_t)(t0 + i) * Dn + k]);
            lo[i] = fmaf(xv, blo, lo[i]);
            hi[i] = fmaf(xv, bhi, hi[i]);
        }
    }

    // rope: exponent = (2*lane)/64 = lane/32
    float f = powf(10000.0f, -(float)lane / 32.0f);
#pragma unroll
    for (int i = 0; i < 8; i++) {
        float ang = (float)(t0 + i) * f;
        float c = cosf(ang), s = sinf(ang);
        krout[(t0 + i) * RDn + lane]      = lo[i] * c - hi[i] * s;
        krout[(t0 + i) * RDn + lane + 32] = hi[i] * c + lo[i] * s;
    }
}

// ---------------------------------------------------------------------------
// In-place RoPE on qr: (T, H*RD); one thread per (t, h, r<32) pair
// ---------------------------------------------------------------------------
__global__ void rope_qr_kernel(float* __restrict__ qr)
{
    int i = blockIdx.x * blockDim.x + threadIdx.x;
    if (i >= Tn * Hn * 32) return;
    int r = i & 31;
    int h = (i >> 5) & (Hn - 1);
    int t = i >> 9;

    float f = powf(10000.0f, -(float)r / 32.0f);
    float ang = (float)t * f;
    float c = cosf(ang), s = sinf(ang);

    int base = t * (Hn * RDn) + h * RDn + r;
    float a = qr[base];
    float b = qr[base + 32];
    qr[base]      = a * c - b * s;
    qr[base + 32] = b * c + a * s;
}

// ---------------------------------------------------------------------------
// Sparse top-k attention: one warp per (t, h); lane j owns selected token j
// ---------------------------------------------------------------------------
__global__ void attn_kernel(const float* __restrict__ q,
                            const float* __restrict__ qr,
                            const float* __restrict__ kmat,
                            const float* __restrict__ vmat,
                            const float* __restrict__ kr,
                            const int*   __restrict__ topk,
                            float* __restrict__ out)
{
    const int warp = (blockIdx.x * blockDim.x + threadIdx.x) >> 5;
    const int lane = threadIdx.x & 31;
    if (warp >= Tn * Hn) return;
    const int t = warp >> 4;        // / H
    const int h = warp & (Hn - 1);  // % H

    const int idx = topk[t * Kn + lane];

    // score for this lane's selected token
    const float* qp = q + (size_t)t * Dn + h * HDn;
    const float* kp = kmat + (size_t)idx * Dn + h * HDn;
    float s = 0.f;
#pragma unroll
    for (int d = 0; d < HDn; d += 4) {
        float4 qv = *reinterpret_cast<const float4*>(qp + d);
        float4 kv = *reinterpret_cast<const float4*>(kp + d);
        s = fmaf(qv.x, kv.x, s); s = fmaf(qv.y, kv.y, s);
        s = fmaf(qv.z, kv.z, s); s = fmaf(qv.w, kv.w, s);
    }
    const float* qrp = qr + (size_t)t * (Hn * RDn) + h * RDn;
    const float* krp = kr + (size_t)idx * RDn;
#pragma unroll
    for (int d = 0; d < RDn; d += 4) {
        float4 a = *reinterpret_cast<const float4*>(qrp + d);
        float4 b = *reinterpret_cast<const float4*>(krp + d);
        s = fmaf(a.x, b.x, s); s = fmaf(a.y, b.y, s);
        s = fmaf(a.z, b.z, s); s = fmaf(a.w, b.w, s);
    }
    s *= SCALE_ATTN;

    // warp softmax over 32 lanes
    float m = s;
#pragma unroll
    for (int o = 16; o; o >>= 1) m = fmaxf(m, __shfl_xor_sync(0xFFFFFFFFu, m, o));
    float e = expf(s - m);
    float sum = e;
#pragma unroll
    for (int o = 16; o; o >>= 1) sum += __shfl_xor_sync(0xFFFFFFFFu, sum, o);
    float w = e / sum;

    // weighted V sum: lane covers d = lane + {0,32,64,96}, coalesced per j
    float acc0 = 0.f, acc1 = 0.f, acc2 = 0.f, acc3 = 0.f;
#pragma unroll
    for (int j = 0; j < Kn; j++) {
        float wj = __shfl_sync(0xFFFFFFFFu, w, j);
        int   ij = __shfl_sync(0xFFFFFFFFu, idx, j);
        const float* vp = vmat + (size_t)ij * Dn + h * HDn;
        acc0 = fmaf(wj, vp[lane],      acc0);
        acc1 = fmaf(wj, vp[lane + 32], acc1);
        acc2 = fmaf(wj, vp[lane + 64], acc2);
        acc3 = fmaf(wj, vp[lane + 96], acc3);
    }
    float* op = out + (size_t)t * Dn + h * HDn;
    op[lane]      = acc0;
    op[lane + 32] = acc1;
    op[lane + 64] = acc2;
    op[lane + 96] = acc3;
}

// ---------------------------------------------------------------------------
// Launcher
// ---------------------------------------------------------------------------
extern "C" void kernel_launch(void* const* d_in, const int* in_sizes, int n_in,
                              void* d_out, int out_size)
{
    const float* x    = (const float*)d_in[0];
    const float* Wqd  = (const float*)d_in[1];
    const float* Wqu  = (const float*)d_in[2];
    const float* Wqr  = (const float*)d_in[3];
    const float* Wkvd = (const float*)d_in[4];
    const float* Wku  = (const float*)d_in[5];
    const float* Wvu  = (const float*)d_in[6];
    const float* Wkr  = (const float*)d_in[7];
    const float* Wo   = (const float*)d_in[8];
    const int*   topk = (const int*)  d_in[9];
    float* out = (float*)d_out;

    float *ql, *ckv, *q, *qr, *k, *v, *kr, *ao;
    cudaGetSymbolAddress((void**)&ql,  g_ql);
    cudaGetSymbolAddress((void**)&ckv, g_ckv);
    cudaGetSymbolAddress((void**)&q,   g_q);
    cudaGetSymbolAddress((void**)&qr,  g_qr);
    cudaGetSymbolAddress((void**)&k,   g_k);
    cudaGetSymbolAddress((void**)&v,   g_v);
    cudaGetSymbolAddress((void**)&kr,  g_kr);
    cudaGetSymbolAddress((void**)&ao,  g_ao);

    dim3 blk(256);

    // ql = x @ Wqd          (2048x2048 @ 2048x512)
    sgemm_kernel<<<dim3(Ln / BN, Tn / BM), blk>>>(x, Wqd, ql, Tn, Ln, Dn);
    // ckv = x @ Wkvd
    sgemm_kernel<<<dim3(Ln / BN, Tn / BM), blk>>>(x, Wkvd, ckv, Tn, Ln, Dn);
    // q = ql @ Wqu          (2048x512 @ 512x2048)
    sgemm_kernel<<<dim3(Dn / BN, Tn / BM), blk>>>(ql, Wqu, q, Tn, Dn, Ln);
    // qr = ql @ Wqr         (2048x512 @ 512x1024)
    sgemm_kernel<<<dim3((Hn * RDn) / BN, Tn / BM), blk>>>(ql, Wqr, qr, Tn, Hn * RDn, Ln);
    // k = ckv @ Wku
    sgemm_kernel<<<dim3(Dn / BN, Tn / BM), blk>>>(ckv, Wku, k, Tn, Dn, Ln);
    // v = ckv @ Wvu
    sgemm_kernel<<<dim3(Dn / BN, Tn / BM), blk>>>(ckv, Wvu, v, Tn, Dn, Ln);

    // kr = rope(x @ Wkr)    (2048x2048 @ 2048x64), fused
    kr_kernel<<<Tn / 8 / 8, 256>>>(x, Wkr, kr);

    // rope qr in place
    rope_qr_kernel<<<(Tn * Hn * 32 + 255) / 256, 256>>>(qr);

    // sparse attention: one warp per (t,h) -> 2048*16 warps
    attn_kernel<<<(Tn * Hn * 32 + 255) / 256, 256>>>(q, qr, k, v, kr, topk, ao);

    // out = ao @ Wo         (2048x2048 @ 2048x2048)
    sgemm_kernel<<<dim3(Dn / BN, Tn / BM), blk>>>(ao, Wo, out, Tn, Dn, Dn);
}

// round 3
// speedup vs baseline: 3.3386x; 3.3386x over previous
#include <cuda_runtime.h>
#include <cuda_bf16.h>
#include <math.h>
#include <stdint.h>

// Problem constants
#define Tn   2048
#define Dn   2048
#define Hn   16
#define HDn  128
#define Ln   512
#define RDn  64
#define Kn   32
#define SCALE_ATTN (0.07216878364870323f)  // 1/sqrt(192)

typedef __nv_bfloat16 bf16;

// ---------------------------------------------------------------------------
// Scratch (static device globals)
// ---------------------------------------------------------------------------
__device__ float g_q [Tn * Dn];
__device__ float g_qr[Tn * Hn * RDn];
__device__ float g_k [Tn * Dn];
__device__ float g_v [Tn * Dn];
__device__ float g_kr[Tn * RDn];
__device__ float g_ao[Tn * Dn];

__device__ bf16 g_x_hi  [Tn * Dn],  g_x_lo  [Tn * Dn];
__device__ bf16 g_ql_hi [Tn * Ln],  g_ql_lo [Tn * Ln];
__device__ bf16 g_ckv_hi[Tn * Ln],  g_ckv_lo[Tn * Ln];
__device__ bf16 g_ao_hi [Tn * Dn],  g_ao_lo [Tn * Dn];

__device__ bf16 g_WqdT_hi [Ln * Dn],        g_WqdT_lo [Ln * Dn];
__device__ bf16 g_WkvdT_hi[Ln * Dn],        g_WkvdT_lo[Ln * Dn];
__device__ bf16 g_WquT_hi [Dn * Ln],        g_WquT_lo [Dn * Ln];
__device__ bf16 g_WqrT_hi [Hn * RDn * Ln],  g_WqrT_lo [Hn * RDn * Ln];
__device__ bf16 g_WkuT_hi [Dn * Ln],        g_WkuT_lo [Dn * Ln];
__device__ bf16 g_WvuT_hi [Dn * Ln],        g_WvuT_lo [Dn * Ln];
__device__ bf16 g_WkrT_hi [RDn * Dn],       g_WkrT_lo [RDn * Dn];
__device__ bf16 g_WoT_hi  [Dn * Dn],        g_WoT_lo  [Dn * Dn];

// ---------------------------------------------------------------------------
// Low-level helpers (all plain sm_80-era PTX -- no 'a'-suffix features)
// ---------------------------------------------------------------------------
__device__ __forceinline__ uint32_t smem_u32_of(const void* p) {
    uint32_t a;
    asm("{ .reg .u64 t; cvta.to.shared.u64 t, %1; cvt.u32.u64 %0, t; }"
        : "=r"(a) : "l"(p));
    return a;
}

__device__ __forceinline__ void cp16(uint32_t saddr, const void* gptr) {
    asm volatile("cp.async.cg.shared.global [%0], [%1], 16;"
                 :: "r"(saddr), "l"(gptr));
}
#define CP_COMMIT() asm volatile("cp.async.commit_group;" ::: "memory")
#define CP_WAIT(N)  asm volatile("cp.async.wait_group %0;" :: "n"(N) : "memory")

__device__ __forceinline__ void ldm_x4(uint32_t* r, uint32_t addr) {
    asm volatile("ldmatrix.sync.aligned.m8n8.x4.shared.b16 {%0,%1,%2,%3}, [%4];"
                 : "=r"(r[0]), "=r"(r[1]), "=r"(r[2]), "=r"(r[3]) : "r"(addr));
}

__device__ __forceinline__ void mma_bf16(float* d, const uint32_t* a, const uint32_t* b) {
    asm volatile("mma.sync.aligned.m16n8k16.row.col.f32.bf16.bf16.f32 "
                 "{%0,%1,%2,%3}, {%4,%5,%6,%7}, {%8,%9}, {%0,%1,%2,%3};"
                 : "+f"(d[0]), "+f"(d[1]), "+f"(d[2]), "+f"(d[3])
                 : "r"(a[0]), "r"(a[1]), "r"(a[2]), "r"(a[3]),
                   "r"(b[0]), "r"(b[1]));
}

// ---------------------------------------------------------------------------
// fp32 -> (hi, lo) bf16 split, elementwise
// ---------------------------------------------------------------------------
__global__ void split_kernel(const float* __restrict__ in,
                             bf16* __restrict__ hi, bf16* __restrict__ lo, int n)
{
    int i = blockIdx.x * blockDim.x + threadIdx.x;
    if (i >= n) return;
    float f = in[i];
    bf16 h = __float2bfloat16(f);
    hi[i] = h;
    lo[i] = __float2bfloat16(f - __bfloat162float(h));
}

// ---------------------------------------------------------------------------
// W [K, N] fp32 -> Wt_hi/Wt_lo [N, K] bf16 (transpose + split)
// ---------------------------------------------------------------------------
__global__ void tsplit_kernel(const float* __restrict__ W,
                              bf16* __restrict__ hi, bf16* __restrict__ lo,
                              int Kd, int N)
{
    __shared__ float tile[32][33];
    int n0 = blockIdx.x * 32, k0 = blockIdx.y * 32;
    int tx = threadIdx.x, ty = threadIdx.y;   // 32 x 8
#pragma unroll
    for (int i = 0; i < 32; i += 8)
        tile[ty + i][tx] = W[(size_t)(k0 + ty + i) * N + n0 + tx];
    __syncthreads();
#pragma unroll
    for (int i = 0; i < 32; i += 8) {
        float f = tile[tx][ty + i];
        bf16 h = __float2bfloat16(f);
        size_t o = (size_t)(n0 + ty + i) * Kd + k0 + tx;
        hi[o] = h;
        lo[o] = __float2bfloat16(f - __bfloat162float(h));
    }
}

// ---------------------------------------------------------------------------
// mma.sync split-bf16 GEMM: C[M,Ntot] = (Ahi+Alo)[M,Kd] @ (Bhi+Blo)[Ntot,Kd]^T
// CTA tile 128 x NT, K-chunk 64 (bf16), 256 threads, 2-stage cp.async pipe.
// SPLIT: emit bf16 hi/lo pair instead of fp32.
// ---------------------------------------------------------------------------
template<int NT, bool SPLIT>
__global__ __launch_bounds__(256, 1)
void mm_kernel(const bf16* __restrict__ Ahi, const bf16* __restrict__ Alo,
               const bf16* __restrict__ Bhi, const bf16* __restrict__ Blo,
               float* __restrict__ C, bf16* __restrict__ Chi, bf16* __restrict__ Clo,
               int Kd, int Ntot)
{
    constexpr int ABYTES = 128 * 128;          // one 128x64-bf16 matrix
    constexpr int BBYTES = NT * 128;
    constexpr int STAGE  = 2 * ABYTES + 2 * BBYTES;
    constexpr int MI = (NT == 128) ? 4 : 2;    // 16-row subtiles per warp
    constexpr int NI = 4;                       // 8-col subtiles per warp

    extern __shared__ __align__(1024) uint8_t smem[];
    const uint32_t sm32 = smem_u32_of(smem);

    const int tid  = threadIdx.x;
    const int wid  = tid >> 5;
    const int lane = tid & 31;
    const int m0 = blockIdx.x * 128;
    const int n0 = blockIdx.y * NT;

    const int mwarp = (NT == 128) ? ((wid & 1) * 64) : ((wid & 3) * 32);
    const int nwarp = (NT == 128) ? ((wid >> 1) * 32) : ((wid >> 2) * 32);

    const int lchunk = tid & 7;      // 16B chunk within 128B row
    const int lrow   = tid >> 3;     // 0..31

    float acc[MI][NI][4];
#pragma unroll
    for (int i = 0; i < MI; i++)
#pragma unroll
        for (int j = 0; j < NI; j++)
#pragma unroll
            for (int r = 0; r < 4; r++) acc[i][j][r] = 0.f;

    const int nch = Kd >> 6;

    auto load_chunk = [&](int c, int s) {
        const uint32_t base = sm32 + s * STAGE;
        const size_t kofs = (size_t)c * 64 + lchunk * 8;
#pragma unroll
        for (int r = 0; r < 128; r += 32) {
            const int row = lrow + r;
            const size_t go = (size_t)(m0 + row) * Kd + kofs;
            const uint32_t so = base + row * 128 + ((lchunk ^ (row & 7)) << 4);
            cp16(so,          Ahi + go);
            cp16(so + ABYTES, Alo + go);
        }
#pragma unroll
        for (int r = 0; r < NT; r += 32) {
            const int row = lrow + r;
            const size_t go = (size_t)(n0 + row) * Kd + kofs;
            const uint32_t so = base + 2 * ABYTES + row * 128 + ((lchunk ^ (row & 7)) << 4);
            cp16(so,          Bhi + go);
            cp16(so + BBYTES, Blo + go);
        }
        CP_COMMIT();
    };

    auto compute_chunk = [&](int s) {
        const uint32_t aBase = sm32 + s * STAGE;
        const uint32_t bBase = aBase + 2 * ABYTES;
#pragma unroll
        for (int ks = 0; ks < 4; ks++) {
            uint32_t aHi[MI][4], aLo[MI][4], bHi[NI][2], bLo[NI][2];
#pragma unroll
            for (int mi = 0; mi < MI; mi++) {
                const int row = mwarp + mi * 16 + (lane & 15);
                const int chunk = ks * 2 + (lane >> 4);
                const uint32_t off = row * 128 + ((chunk ^ (row & 7)) << 4);
                ldm_x4(aHi[mi], aBase + off);
                ldm_x4(aLo[mi], aBase + ABYTES + off);
            }
#pragma unroll
            for (int nj = 0; nj < NI / 2; nj++) {
                const int row = nwarp + nj * 16 + ((lane >> 4) << 3) + (lane & 7);
                const int chunk = ks * 2 + ((lane >> 3) & 1);
                const uint32_t off = row * 128 + ((chunk ^ (row & 7)) << 4);
                uint32_t r4[4];
                ldm_x4(r4, bBase + off);
                bHi[nj * 2][0] = r4[0]; bHi[nj * 2][1] = r4[1];
                bHi[nj * 2 + 1][0] = r4[2]; bHi[nj * 2 + 1][1] = r4[3];
                ldm_x4(r4, bBase + BBYTES + off);
                bLo[nj * 2][0] = r4[0]; bLo[nj * 2][1] = r4[1];
                bLo[nj * 2 + 1][0] = r4[2]; bLo[nj * 2 + 1][1] = r4[3];
            }
#pragma unroll
            for (int mi = 0; mi < MI; mi++)
#pragma unroll
                for (int ni = 0; ni < NI; ni++) {
                    mma_bf16(acc[mi][ni], aHi[mi], bHi[ni]);
                    mma_bf16(acc[mi][ni], aHi[mi], bLo[ni]);
                    mma_bf16(acc[mi][ni], aLo[mi], bHi[ni]);
                }
        }
    };

    // 2-stage pipeline
    load_chunk(0, 0);
    for (int c = 0; c < nch; c++) {
        if (c + 1 < nch) {
            load_chunk(c + 1, (c + 1) & 1);
            CP_WAIT(1);
        } else {
            CP_WAIT(0);
        }
        __syncthreads();
        compute_chunk(c & 1);
        __syncthreads();
    }

    // epilogue
#pragma unroll
    for (int mi = 0; mi < MI; mi++)
#pragma unroll
        for (int ni = 0; ni < NI; ni++) {
            const int row = m0 + mwarp + mi * 16 + (lane >> 2);
            const int col = n0 + nwarp + ni * 8 + ((lane & 3) << 1);
            if (SPLIT) {
                float f0 = acc[mi][ni][0], f1 = acc[mi][ni][1];
                float f2 = acc[mi][ni][2], f3 = acc[mi][ni][3];
                bf16 h0 = __float2bfloat16(f0), h1 = __float2bfloat16(f1);
                bf16 h2 = __float2bfloat16(f2), h3 = __float2bfloat16(f3);
                bf16 l0 = __float2bfloat16(f0 - __bfloat162float(h0));
                bf16 l1 = __float2bfloat16(f1 - __bfloat162float(h1));
                bf16 l2 = __float2bfloat16(f2 - __bfloat162float(h2));
                bf16 l3 = __float2bfloat16(f3 - __bfloat162float(h3));
                *reinterpret_cast<__nv_bfloat162*>(Chi + (size_t)row * Ntot + col) =
                    __halves2bfloat162(h0, h1);
                *reinterpret_cast<__nv_bfloat162*>(Clo + (size_t)row * Ntot + col) =
                    __halves2bfloat162(l0, l1);
                *reinterpret_cast<__nv_bfloat162*>(Chi + (size_t)(row + 8) * Ntot + col) =
                    __halves2bfloat162(h2, h3);
                *reinterpret_cast<__nv_bfloat162*>(Clo + (size_t)(row + 8) * Ntot + col) =
                    __halves2bfloat162(l2, l3);
            } else {
                *reinterpret_cast<float2*>(C + (size_t)row * Ntot + col) =
                    make_float2(acc[mi][ni][0], acc[mi][ni][1]);
                *reinterpret_cast<float2*>(C + (size_t)(row + 8) * Ntot + col) =
                    make_float2(acc[mi][ni][2], acc[mi][ni][3]);
            }
        }
}

// ---------------------------------------------------------------------------
// RoPE kernels
// ---------------------------------------------------------------------------
__global__ void rope_qr_kernel(float* __restrict__ qr)
{
    int i = blockIdx.x * blockDim.x + threadIdx.x;
    if (i >= Tn * Hn * 32) return;
    int r = i & 31;
    int h = (i >> 5) & (Hn - 1);
    int t = i >> 9;
    float f = powf(10000.0f, -(float)r / 32.0f);
    float ang = (float)t * f;
    float c = cosf(ang), s = sinf(ang);
    int base = t * (Hn * RDn) + h * RDn + r;
    float a = qr[base];
    float b = qr[base + 32];
    qr[base]      = a * c - b * s;
    qr[base + 32] = b * c + a * s;
}

__global__ void rope_kr_kernel(float* __restrict__ kr)
{
    int i = blockIdx.x * blockDim.x + threadIdx.x;
    if (i >= Tn * 32) return;
    int r = i & 31;
    int t = i >> 5;
    float f = powf(10000.0f, -(float)r / 32.0f);
    float ang = (float)t * f;
    float c = cosf(ang), s = sinf(ang);
    int base = t * RDn + r;
    float a = kr[base];
    float b = kr[base + 32];
    kr[base]      = a * c - b * s;
    kr[base + 32] = b * c + a * s;
}

// ---------------------------------------------------------------------------
// Sparse top-k attention: one warp per (t, h); lane j owns selected token j
// ---------------------------------------------------------------------------
__global__ void attn_kernel(const float* __restrict__ q,
                            const float* __restrict__ qr,
                            const float* __restrict__ kmat,
                            const float* __restrict__ vmat,
                            const float* __restrict__ kr,
                            const int*   __restrict__ topk,
                            float* __restrict__ out)
{
    const int warp = (blockIdx.x * blockDim.x + threadIdx.x) >> 5;
    const int lane = threadIdx.x & 31;
    if (warp >= Tn * Hn) return;
    const int t = warp >> 4;
    const int h = warp & (Hn - 1);

    const int idx = topk[t * Kn + lane];

    const float* qp = q + (size_t)t * Dn + h * HDn;
    const float* kp = kmat + (size_t)idx * Dn + h * HDn;
    float s = 0.f;
#pragma unroll
    for (int d = 0; d < HDn; d += 4) {
        float4 qv = *reinterpret_cast<const float4*>(qp + d);
        float4 kv = *reinterpret_cast<const float4*>(kp + d);
        s = fmaf(qv.x, kv.x, s); s = fmaf(qv.y, kv.y, s);
        s = fmaf(qv.z, kv.z, s); s = fmaf(qv.w, kv.w, s);
    }
    const float* qrp = qr + (size_t)t * (Hn * RDn) + h * RDn;
    const float* krp = kr + (size_t)idx * RDn;
#pragma unroll
    for (int d = 0; d < RDn; d += 4) {
        float4 a = *reinterpret_cast<const float4*>(qrp + d);
        float4 b = *reinterpret_cast<const float4*>(krp + d);
        s = fmaf(a.x, b.x, s); s = fmaf(a.y, b.y, s);
        s = fmaf(a.z, b.z, s); s = fmaf(a.w, b.w, s);
    }
    s *= SCALE_ATTN;

    float m = s;
#pragma unroll
    for (int o = 16; o; o >>= 1) m = fmaxf(m, __shfl_xor_sync(0xFFFFFFFFu, m, o));
    float e = expf(s - m);
    float sum = e;
#pragma unroll
    for (int o = 16; o; o >>= 1) sum += __shfl_xor_sync(0xFFFFFFFFu, sum, o);
    float w = e / sum;

    float acc0 = 0.f, acc1 = 0.f, acc2 = 0.f, acc3 = 0.f;
#pragma unroll
    for (int j = 0; j < Kn; j++) {
        float wj = __shfl_sync(0xFFFFFFFFu, w, j);
        int   ij = __shfl_sync(0xFFFFFFFFu, idx, j);
        const float* vp = vmat + (size_t)ij * Dn + h * HDn;
        acc0 = fmaf(wj, vp[lane],      acc0);
        acc1 = fmaf(wj, vp[lane + 32], acc1);
        acc2 = fmaf(wj, vp[lane + 64], acc2);
        acc3 = fmaf(wj, vp[lane + 96], acc3);
    }
    float* op = out + (size_t)t * Dn + h * HDn;
    op[lane]      = acc0;
    op[lane + 32] = acc1;
    op[lane + 64] = acc2;
    op[lane + 96] = acc3;
}

// ---------------------------------------------------------------------------
// Launcher
// ---------------------------------------------------------------------------
extern "C" void kernel_launch(void* const* d_in, const int* in_sizes, int n_in,
                              void* d_out, int out_size)
{
    const float* x    = (const float*)d_in[0];
    const float* Wqd  = (const float*)d_in[1];
    const float* Wqu  = (const float*)d_in[2];
    const float* Wqr  = (const float*)d_in[3];
    const float* Wkvd = (const float*)d_in[4];
    const float* Wku  = (const float*)d_in[5];
    const float* Wvu  = (const float*)d_in[6];
    const float* Wkr  = (const float*)d_in[7];
    const float* Wo   = (const float*)d_in[8];
    const int*   topk = (const int*)  d_in[9];
    float* out = (float*)d_out;

    float *q, *qr, *k, *v, *kr, *ao;
    cudaGetSymbolAddress((void**)&q,  g_q);
    cudaGetSymbolAddress((void**)&qr, g_qr);
    cudaGetSymbolAddress((void**)&k,  g_k);
    cudaGetSymbolAddress((void**)&v,  g_v);
    cudaGetSymbolAddress((void**)&kr, g_kr);
    cudaGetSymbolAddress((void**)&ao, g_ao);

    bf16 *x_hi, *x_lo, *ql_hi, *ql_lo, *ckv_hi, *ckv_lo, *ao_hi, *ao_lo;
    cudaGetSymbolAddress((void**)&x_hi,   g_x_hi);
    cudaGetSymbolAddress((void**)&x_lo,   g_x_lo);
    cudaGetSymbolAddress((void**)&ql_hi,  g_ql_hi);
    cudaGetSymbolAddress((void**)&ql_lo,  g_ql_lo);
    cudaGetSymbolAddress((void**)&ckv_hi, g_ckv_hi);
    cudaGetSymbolAddress((void**)&ckv_lo, g_ckv_lo);
    cudaGetSymbolAddress((void**)&ao_hi,  g_ao_hi);
    cudaGetSymbolAddress((void**)&ao_lo,  g_ao_lo);

    bf16 *WqdT_hi, *WqdT_lo, *WkvdT_hi, *WkvdT_lo, *WquT_hi, *WquT_lo,
         *WqrT_hi, *WqrT_lo, *WkuT_hi, *WkuT_lo, *WvuT_hi, *WvuT_lo,
         *WkrT_hi, *WkrT_lo, *WoT_hi, *WoT_lo;
    cudaGetSymbolAddress((void**)&WqdT_hi,  g_WqdT_hi);
    cudaGetSymbolAddress((void**)&WqdT_lo,  g_WqdT_lo);
    cudaGetSymbolAddress((void**)&WkvdT_hi, g_WkvdT_hi);
    cudaGetSymbolAddress((void**)&WkvdT_lo, g_WkvdT_lo);
    cudaGetSymbolAddress((void**)&WquT_hi,  g_WquT_hi);
    cudaGetSymbolAddress((void**)&WquT_lo,  g_WquT_lo);
    cudaGetSymbolAddress((void**)&WqrT_hi,  g_WqrT_hi);
    cudaGetSymbolAddress((void**)&WqrT_lo,  g_WqrT_lo);
    cudaGetSymbolAddress((void**)&WkuT_hi,  g_WkuT_hi);
    cudaGetSymbolAddress((void**)&WkuT_lo,  g_WkuT_lo);
    cudaGetSymbolAddress((void**)&WvuT_hi,  g_WvuT_hi);
    cudaGetSymbolAddress((void**)&WvuT_lo,  g_WvuT_lo);
    cudaGetSymbolAddress((void**)&WkrT_hi,  g_WkrT_hi);
    cudaGetSymbolAddress((void**)&WkrT_lo,  g_WkrT_lo);
    cudaGetSymbolAddress((void**)&WoT_hi,   g_WoT_hi);
    cudaGetSymbolAddress((void**)&WoT_lo,   g_WoT_lo);

    constexpr int SMEM_128 = 2 * (2 * 128 * 128 + 2 * 128 * 128); // 131072
    constexpr int SMEM_64  = 2 * (2 * 128 * 128 + 2 * 64 * 128);  //  98304
    cudaFuncSetAttribute(mm_kernel<128, false>, cudaFuncAttributeMaxDynamicSharedMemorySize, SMEM_128);
    cudaFuncSetAttribute(mm_kernel<128, true>,  cudaFuncAttributeMaxDynamicSharedMemorySize, SMEM_128);
    cudaFuncSetAttribute(mm_kernel<64,  false>, cudaFuncAttributeMaxDynamicSharedMemorySize, SMEM_64);

    // 1) split x
    split_kernel<<<(Tn * Dn + 255) / 256, 256>>>(x, x_hi, x_lo, Tn * Dn);

    // 2) transpose+split weights: W[K,N] -> Wt[N,K]
    dim3 tb(32, 8);
    tsplit_kernel<<<dim3(Ln / 32,        Dn / 32), tb>>>(Wqd,  WqdT_hi,  WqdT_lo,  Dn, Ln);
    tsplit_kernel<<<dim3(Ln / 32,        Dn / 32), tb>>>(Wkvd, WkvdT_hi, WkvdT_lo, Dn, Ln);
    tsplit_kernel<<<dim3(Dn / 32,        Ln / 32), tb>>>(Wqu,  WquT_hi,  WquT_lo,  Ln, Dn);
    tsplit_kernel<<<dim3(Hn * RDn / 32,  Ln / 32), tb>>>(Wqr,  WqrT_hi,  WqrT_lo,  Ln, Hn * RDn);
    tsplit_kernel<<<dim3(Dn / 32,        Ln / 32), tb>>>(Wku,  WkuT_hi,  WkuT_lo,  Ln, Dn);
    tsplit_kernel<<<dim3(Dn / 32,        Ln / 32), tb>>>(Wvu,  WvuT_hi,  WvuT_lo,  Ln, Dn);
    tsplit_kernel<<<dim3(RDn / 32,       Dn / 32), tb>>>(Wkr,  WkrT_hi,  WkrT_lo,  Dn, RDn);
    tsplit_kernel<<<dim3(Dn / 32,        Dn / 32), tb>>>(Wo,   WoT_hi,   WoT_lo,   Dn, Dn);

    // 3) down-projections (emit split bf16 directly)
    mm_kernel<128, true><<<dim3(Tn / 128, Ln / 128), 256, SMEM_128>>>(
        x_hi, x_lo, WqdT_hi, WqdT_lo, nullptr, ql_hi, ql_lo, Dn, Ln);
    mm_kernel<128, true><<<dim3(Tn / 128, Ln / 128), 256, SMEM_128>>>(
        x_hi, x_lo, WkvdT_hi, WkvdT_lo, nullptr, ckv_hi, ckv_lo, Dn, Ln);

    // 4) up-projections (fp32 out)
    mm_kernel<128, false><<<dim3(Tn / 128, Dn / 128), 256, SMEM_128>>>(
        ql_hi, ql_lo, WquT_hi, WquT_lo, q, nullptr, nullptr, Ln, Dn);
    mm_kernel<128, false><<<dim3(Tn / 128, (Hn * RDn) / 128), 256, SMEM_128>>>(
        ql_hi, ql_lo, WqrT_hi, WqrT_lo, qr, nullptr, nullptr, Ln, Hn * RDn);
    mm_kernel<128, false><<<dim3(Tn / 128, Dn / 128), 256, SMEM_128>>>(
        ckv_hi, ckv_lo, WkuT_hi, WkuT_lo, k, nullptr, nullptr, Ln, Dn);
    mm_kernel<128, false><<<dim3(Tn / 128, Dn / 128), 256, SMEM_128>>>(
        ckv_hi, ckv_lo, WvuT_hi, WvuT_lo, v, nullptr, nullptr, Ln, Dn);
    mm_kernel<64, false><<<dim3(Tn / 128, 1), 256, SMEM_64>>>(
        x_hi, x_lo, WkrT_hi, WkrT_lo, kr, nullptr, nullptr, Dn, RDn);

    // 5) rope
    rope_qr_kernel<<<(Tn * Hn * 32 + 255) / 256, 256>>>(qr);
    rope_kr_kernel<<<(Tn * 32 + 255) / 256, 256>>>(kr);

    // 6) sparse attention
    attn_kernel<<<(Tn * Hn * 32 + 255) / 256, 256>>>(q, qr, k, v, kr, topk, ao);

    // 7) split ao, output projection
    split_kernel<<<(Tn * Dn + 255) / 256, 256>>>(ao, ao_hi, ao_lo, Tn * Dn);
    mm_kernel<128, false><<<dim3(Tn / 128, Dn / 128), 256, SMEM_128>>>(
        ao_hi, ao_lo, WoT_hi, WoT_lo, out, nullptr, nullptr, Dn, Dn);
}

// round 4
// speedup vs baseline: 4.1128x; 1.2319x over previous
#include <cuda_runtime.h>
#include <cuda_bf16.h>
#include <math.h>
#include <stdint.h>

// Problem constants
#define Tn   2048
#define Dn   2048
#define Hn   16
#define HDn  128
#define Ln   512
#define RDn  64
#define Kn   32
#define KSPLIT 8
#define SCALE_ATTN (0.07216878364870323f)  // 1/sqrt(192)

typedef __nv_bfloat16 bf16;

// ---------------------------------------------------------------------------
// Scratch (static device globals)
// ---------------------------------------------------------------------------
__device__ float g_q  [Tn * Dn];
__device__ float g_qr [Tn * Hn * RDn];
__device__ float g_k  [Tn * Dn];
__device__ float g_v  [Tn * Dn];
__device__ float g_kr [Tn * RDn];
__device__ float g_krp[KSPLIT * Tn * RDn];   // kr split-K partials

__device__ bf16 g_x_hi  [Tn * Dn],  g_x_lo  [Tn * Dn];
__device__ bf16 g_ql_hi [Tn * Ln],  g_ql_lo [Tn * Ln];
__device__ bf16 g_ckv_hi[Tn * Ln],  g_ckv_lo[Tn * Ln];
__device__ bf16 g_ao_hi [Tn * Dn],  g_ao_lo [Tn * Dn];

__device__ bf16 g_WqdT_hi [Ln * Dn],        g_WqdT_lo [Ln * Dn];
__device__ bf16 g_WkvdT_hi[Ln * Dn],        g_WkvdT_lo[Ln * Dn];
__device__ bf16 g_WquT_hi [Dn * Ln],        g_WquT_lo [Dn * Ln];
__device__ bf16 g_WqrT_hi [Hn * RDn * Ln],  g_WqrT_lo [Hn * RDn * Ln];
__device__ bf16 g_WkuT_hi [Dn * Ln],        g_WkuT_lo [Dn * Ln];
__device__ bf16 g_WvuT_hi [Dn * Ln],        g_WvuT_lo [Dn * Ln];
__device__ bf16 g_WkrT_hi [RDn * Dn],       g_WkrT_lo [RDn * Dn];
__device__ bf16 g_WoT_hi  [Dn * Dn],        g_WoT_lo  [Dn * Dn];

// ---------------------------------------------------------------------------
// Low-level helpers (plain sm_80-era PTX only — no 'a'-suffix features)
// ---------------------------------------------------------------------------
__device__ __forceinline__ uint32_t smem_u32_of(const void* p) {
    uint32_t a;
    asm("{ .reg .u64 t; cvta.to.shared.u64 t, %1; cvt.u32.u64 %0, t; }"
        : "=r"(a) : "l"(p));
    return a;
}

__device__ __forceinline__ void cp16(uint32_t saddr, const void* gptr) {
    asm volatile("cp.async.cg.shared.global [%0], [%1], 16;"
                 :: "r"(saddr), "l"(gptr));
}
#define CP_COMMIT() asm volatile("cp.async.commit_group;" ::: "memory")
#define CP_WAIT0()  asm volatile("cp.async.wait_group 0;" ::: "memory")
#define CP_WAIT1()  asm volatile("cp.async.wait_group 1;" ::: "memory")

__device__ __forceinline__ void ldm_x4(uint32_t* r, uint32_t addr) {
    asm volatile("ldmatrix.sync.aligned.m8n8.x4.shared.b16 {%0,%1,%2,%3}, [%4];"
                 : "=r"(r[0]), "=r"(r[1]), "=r"(r[2]), "=r"(r[3]) : "r"(addr));
}

__device__ __forceinline__ void mma_bf16(float* d, const uint32_t* a, const uint32_t* b) {
    asm volatile("mma.sync.aligned.m16n8k16.row.col.f32.bf16.bf16.f32 "
                 "{%0,%1,%2,%3}, {%4,%5,%6,%7}, {%8,%9}, {%0,%1,%2,%3};"
                 : "+f"(d[0]), "+f"(d[1]), "+f"(d[2]), "+f"(d[3])
                 : "r"(a[0]), "r"(a[1]), "r"(a[2]), "r"(a[3]),
                   "r"(b[0]), "r"(b[1]));
}

// ---------------------------------------------------------------------------
// Core split-bf16 mma.sync GEMM tile:
//   C[128 x NT] @ (m0, n0) = (Ahi+Alo)[128, K] * (Bhi+Blo)[NT, K]^T
// K iterated in chunks of 64 starting at element kbase, nch chunks.
// 3-stage cp.async pipeline, 256 threads.
// EPI: 0 = fp32 store to C; 1 = bf16 hi/lo split store to Chi/Clo.
// ---------------------------------------------------------------------------
template<int NT, int EPI>
__device__ __forceinline__ void mm_core(
    const bf16* __restrict__ Ahi, const bf16* __restrict__ Alo,
    const bf16* __restrict__ Bhi, const bf16* __restrict__ Blo,
    float* __restrict__ C, bf16* __restrict__ Chi, bf16* __restrict__ Clo,
    int Kd, int Ntot, int m0, int n0, int kbase, int nch, uint8_t* smem)
{
    constexpr int ABYTES = 128 * 128;
    constexpr int BBYTES = NT * 128;
    constexpr int STAGE  = 2 * ABYTES + 2 * BBYTES;
    constexpr int MI = (NT == 128) ? 4 : 2;
    constexpr int NI = 4;

    const uint32_t sm32 = smem_u32_of(smem);
    const int tid  = threadIdx.x;
    const int wid  = tid >> 5;
    const int lane = tid & 31;

    const int mwarp = (NT == 128) ? ((wid & 1) * 64) : ((wid & 3) * 32);
    const int nwarp = (NT == 128) ? ((wid >> 1) * 32) : ((wid >> 2) * 32);

    const int lchunk = tid & 7;
    const int lrow   = tid >> 3;

    float acc[MI][NI][4];
#pragma unroll
    for (int i = 0; i < MI; i++)
#pragma unroll
        for (int j = 0; j < NI; j++)
#pragma unroll
            for (int r = 0; r < 4; r++) acc[i][j][r] = 0.f;

    auto load_chunk = [&](int c, int s) {
        const uint32_t base = sm32 + s * STAGE;
        const size_t kofs = (size_t)kbase + (size_t)c * 64 + lchunk * 8;
#pragma unroll
        for (int r = 0; r < 128; r += 32) {
            const int row = lrow + r;
            const size_t go = (size_t)(m0 + row) * Kd + kofs;
            const uint32_t so = base + row * 128 + ((lchunk ^ (row & 7)) << 4);
            cp16(so,          Ahi + go);
            cp16(so + ABYTES, Alo + go);
        }
#pragma unroll
        for (int r = 0; r < NT; r += 32) {
            const int row = lrow + r;
            const size_t go = (size_t)(n0 + row) * Kd + kofs;
            const uint32_t so = base + 2 * ABYTES + row * 128 + ((lchunk ^ (row & 7)) << 4);
            cp16(so,          Bhi + go);
            cp16(so + BBYTES, Blo + go);
        }
        CP_COMMIT();
    };

    auto compute_chunk = [&](int s) {
        const uint32_t aBase = sm32 + s * STAGE;
        const uint32_t bBase = aBase + 2 * ABYTES;
#pragma unroll
        for (int ks = 0; ks < 4; ks++) {
            uint32_t aHi[MI][4], aLo[MI][4], bHi[NI][2], bLo[NI][2];
#pragma unroll
            for (int mi = 0; mi < MI; mi++) {
                const int row = mwarp + mi * 16 + (lane & 15);
                const int chunk = ks * 2 + (lane >> 4);
                const uint32_t off = row * 128 + ((chunk ^ (row & 7)) << 4);
                ldm_x4(aHi[mi], aBase + off);
                ldm_x4(aLo[mi], aBase + ABYTES + off);
            }
#pragma unroll
            for (int nj = 0; nj < NI / 2; nj++) {
                const int row = nwarp + nj * 16 + ((lane >> 4) << 3) + (lane & 7);
                const int chunk = ks * 2 + ((lane >> 3) & 1);
                const uint32_t off = row * 128 + ((chunk ^ (row & 7)) << 4);
                uint32_t r4[4];
                ldm_x4(r4, bBase + off);
                bHi[nj * 2][0] = r4[0]; bHi[nj * 2][1] = r4[1];
                bHi[nj * 2 + 1][0] = r4[2]; bHi[nj * 2 + 1][1] = r4[3];
                ldm_x4(r4, bBase + BBYTES + off);
                bLo[nj * 2][0] = r4[0]; bLo[nj * 2][1] = r4[1];
                bLo[nj * 2 + 1][0] = r4[2]; bLo[nj * 2 + 1][1] = r4[3];
            }
#pragma unroll
            for (int mi = 0; mi < MI; mi++)
#pragma unroll
                for (int ni = 0; ni < NI; ni++) {
                    mma_bf16(acc[mi][ni], aHi[mi], bHi[ni]);
                    mma_bf16(acc[mi][ni], aHi[mi], bLo[ni]);
                    mma_bf16(acc[mi][ni], aLo[mi], bHi[ni]);
                }
        }
    };

    // 3-stage pipeline
    load_chunk(0, 0);
    if (nch > 1) load_chunk(1, 1);
    for (int c = 0; c < nch; c++) {
        if (c + 1 < nch) { CP_WAIT1(); } else { CP_WAIT0(); }
        __syncthreads();
        if (c + 2 < nch) load_chunk(c + 2, (c + 2) % 3);
        compute_chunk(c % 3);
    }

    // epilogue
#pragma unroll
    for (int mi = 0; mi < MI; mi++)
#pragma unroll
        for (int ni = 0; ni < NI; ni++) {
            const int row = m0 + mwarp + mi * 16 + (lane >> 2);
            const int col = n0 + nwarp + ni * 8 + ((lane & 3) << 1);
            if (EPI == 1) {
                float f0 = acc[mi][ni][0], f1 = acc[mi][ni][1];
                float f2 = acc[mi][ni][2], f3 = acc[mi][ni][3];
                bf16 h0 = __float2bfloat16(f0), h1 = __float2bfloat16(f1);
                bf16 h2 = __float2bfloat16(f2), h3 = __float2bfloat16(f3);
                bf16 l0 = __float2bfloat16(f0 - __bfloat162float(h0));
                bf16 l1 = __float2bfloat16(f1 - __bfloat162float(h1));
                bf16 l2 = __float2bfloat16(f2 - __bfloat162float(h2));
                bf16 l3 = __float2bfloat16(f3 - __bfloat162float(h3));
                *reinterpret_cast<__nv_bfloat162*>(Chi + (size_t)row * Ntot + col) =
                    __halves2bfloat162(h0, h1);
                *reinterpret_cast<__nv_bfloat162*>(Clo + (size_t)row * Ntot + col) =
                    __halves2bfloat162(l0, l1);
                *reinterpret_cast<__nv_bfloat162*>(Chi + (size_t)(row + 8) * Ntot + col) =
                    __halves2bfloat162(h2, h3);
                *reinterpret_cast<__nv_bfloat162*>(Clo + (size_t)(row + 8) * Ntot + col) =
                    __halves2bfloat162(l2, l3);
            } else {
                *reinterpret_cast<float2*>(C + (size_t)row * Ntot + col) =
                    make_float2(acc[mi][ni][0], acc[mi][ni][1]);
                *reinterpret_cast<float2*>(C + (size_t)(row + 8) * Ntot + col) =
                    make_float2(acc[mi][ni][2], acc[mi][ni][3]);
            }
        }
}

// ---------------------------------------------------------------------------
// GEMM wrapper kernels (merged launches for full-wave utilization)
// ---------------------------------------------------------------------------
// Down-projections: ql = x@Wqd, ckv = x@Wkvd; 2 segments x 64 CTAs = 128 CTAs
__global__ __launch_bounds__(256, 1)
void mm_down_kernel(const bf16* __restrict__ xhi, const bf16* __restrict__ xlo,
                    const bf16* __restrict__ Bqhi, const bf16* __restrict__ Bqlo,
                    const bf16* __restrict__ Bkhi, const bf16* __restrict__ Bklo,
                    bf16* __restrict__ qlhi, bf16* __restrict__ qllo,
                    bf16* __restrict__ ckvhi, bf16* __restrict__ ckvlo)
{
    extern __shared__ __align__(1024) uint8_t smem[];
    const int bx = blockIdx.x;
    const int seg = bx >> 6;
    const int b = bx & 63;
    const int m0 = (b & 15) * 128;
    const int n0 = (b >> 4) * 128;
    if (seg == 0)
        mm_core<128, 1>(xhi, xlo, Bqhi, Bqlo, nullptr, qlhi, qllo,
                        Dn, Ln, m0, n0, 0, 32, smem);
    else
        mm_core<128, 1>(xhi, xlo, Bkhi, Bklo, nullptr, ckvhi, ckvlo,
                        Dn, Ln, m0, n0, 0, 32, smem);
}

// Up-projections: q, qr, k, v; segments 256+128+256+256 = 896 CTAs
__global__ __launch_bounds__(256, 1)
void mm_up_kernel(const bf16* __restrict__ qlhi, const bf16* __restrict__ qllo,
                  const bf16* __restrict__ ckvhi, const bf16* __restrict__ ckvlo,
                  const bf16* __restrict__ Wquhi, const bf16* __restrict__ Wqulo,
                  const bf16* __restrict__ Wqrhi, const bf16* __restrict__ Wqrlo,
                  const bf16* __restrict__ Wkuhi, const bf16* __restrict__ Wkulo,
                  const bf16* __restrict__ Wvuhi, const bf16* __restrict__ Wvulo,
                  float* __restrict__ q, float* __restrict__ qr,
                  float* __restrict__ k, float* __restrict__ v)
{
    extern __shared__ __align__(1024) uint8_t smem[];
    const int bx = blockIdx.x;
    if (bx < 256) {
        mm_core<128, 0>(qlhi, qllo, Wquhi, Wqulo, q, nullptr, nullptr,
                        Ln, Dn, (bx & 15) * 128, (bx >> 4) * 128, 0, 8, smem);
    } else if (bx < 384) {
        const int b = bx - 256;
        mm_core<128, 0>(qlhi, qllo, Wqrhi, Wqrlo, qr, nullptr, nullptr,
                        Ln, Hn * RDn, (b & 15) * 128, (b >> 4) * 128, 0, 8, smem);
    } else if (bx < 640) {
        const int b = bx - 384;
        mm_core<128, 0>(ckvhi, ckvlo, Wkuhi, Wkulo, k, nullptr, nullptr,
                        Ln, Dn, (b & 15) * 128, (b >> 4) * 128, 0, 8, smem);
    } else {
        const int b = bx - 640;
        mm_core<128, 0>(ckvhi, ckvlo, Wvuhi, Wvulo, v, nullptr, nullptr,
                        Ln, Dn, (b & 15) * 128, (b >> 4) * 128, 0, 8, smem);
    }
}

// kr partials: split-K x 8, 16 M-tiles -> 128 CTAs, NT=64
__global__ __launch_bounds__(256, 1)
void mm_kr_kernel(const bf16* __restrict__ xhi, const bf16* __restrict__ xlo,
                  const bf16* __restrict__ Bhi, const bf16* __restrict__ Blo,
                  float* __restrict__ krp)
{
    extern __shared__ __align__(1024) uint8_t smem[];
    const int bx = blockIdx.x;
    const int mt = bx & 15;
    const int ks = bx >> 4;
    mm_core<64, 0>(xhi, xlo, Bhi, Blo, krp + (size_t)ks * Tn * RDn,
                   nullptr, nullptr,
                   Dn, RDn, mt * 128, 0, ks * (Dn / KSPLIT), (Dn / KSPLIT) / 64, smem);
}

// output projection: out = ao @ Wo; 256 CTAs
__global__ __launch_bounds__(256, 1)
void mm_wo_kernel(const bf16* __restrict__ aohi, const bf16* __restrict__ aolo,
                  const bf16* __restrict__ Bhi, const bf16* __restrict__ Blo,
                  float* __restrict__ out)
{
    extern __shared__ __align__(1024) uint8_t smem[];
    const int bx = blockIdx.x;
    mm_core<128, 0>(aohi, aolo, Bhi, Blo, out, nullptr, nullptr,
                    Dn, Dn, (bx & 15) * 128, (bx >> 4) * 128, 0, 32, smem);
}

// ---------------------------------------------------------------------------
// fp32 -> (hi, lo) bf16 split, elementwise
// ---------------------------------------------------------------------------
__global__ void split_kernel(const float* __restrict__ in,
                             bf16* __restrict__ hi, bf16* __restrict__ lo, int n)
{
    int i = blockIdx.x * blockDim.x + threadIdx.x;
    if (i >= n) return;
    float f = in[i];
    bf16 h = __float2bfloat16(f);
    hi[i] = h;
    lo[i] = __float2bfloat16(f - __bfloat162float(h));
}

// ---------------------------------------------------------------------------
// W [K, N] fp32 -> Wt_hi/Wt_lo [N, K] bf16 (transpose + split)
// ---------------------------------------------------------------------------
__global__ void tsplit_kernel(const float* __restrict__ W,
                              bf16* __restrict__ hi, bf16* __restrict__ lo,
                              int Kd, int N)
{
    __shared__ float tile[32][33];
    int n0 = blockIdx.x * 32, k0 = blockIdx.y * 32;
    int tx = threadIdx.x, ty = threadIdx.y;   // 32 x 8
#pragma unroll
    for (int i = 0; i < 32; i += 8)
        tile[ty + i][tx] = W[(size_t)(k0 + ty + i) * N + n0 + tx];
    __syncthreads();
#pragma unroll
    for (int i = 0; i < 32; i += 8) {
        float f = tile[tx][ty + i];
        bf16 h = __float2bfloat16(f);
        size_t o = (size_t)(n0 + ty + i) * Kd + k0 + tx;
        hi[o] = h;
        lo[o] = __float2bfloat16(f - __bfloat162float(h));
    }
}

// ---------------------------------------------------------------------------
// RoPE kernels
// ---------------------------------------------------------------------------
__global__ void rope_qr_kernel(float* __restrict__ qr)
{
    int i = blockIdx.x * blockDim.x + threadIdx.x;
    if (i >= Tn * Hn * 32) return;
    int r = i & 31;
    int h = (i >> 5) & (Hn - 1);
    int t = i >> 9;
    float f = powf(10000.0f, -(float)r / 32.0f);
    float ang = (float)t * f;
    float c = cosf(ang), s = sinf(ang);
    int base = t * (Hn * RDn) + h * RDn + r;
    float a = qr[base];
    float b = qr[base + 32];
    qr[base]      = a * c - b * s;
    qr[base + 32] = b * c + a * s;
}

// sum kr split-K partials, apply rope
__global__ void rope_kr_reduce_kernel(const float* __restrict__ krp,
                                      float* __restrict__ kr)
{
    int i = blockIdx.x * blockDim.x + threadIdx.x;
    if (i >= Tn * 32) return;
    int r = i & 31;
    int t = i >> 5;
    float a = 0.f, b = 0.f;
#pragma unroll
    for (int s = 0; s < KSPLIT; s++) {
        a += krp[(size_t)s * Tn * RDn + t * RDn + r];
        b += krp[(size_t)s * Tn * RDn + t * RDn + r + 32];
    }
    float f = powf(10000.0f, -(float)r / 32.0f);
    float ang = (float)t * f;
    float c = cosf(ang), sn = sinf(ang);
    kr[t * RDn + r]      = a * c - b * sn;
    kr[t * RDn + r + 32] = b * c + a * sn;
}

// ---------------------------------------------------------------------------
// Sparse top-k attention: one warp per (t, h); lane j owns selected token j.
// Emits ao directly as bf16 hi/lo split (consumed by Wo GEMM).
// ---------------------------------------------------------------------------
__global__ void attn_kernel(const float* __restrict__ q,
                            const float* __restrict__ qr,
                            const float* __restrict__ kmat,
                            const float* __restrict__ vmat,
                            const float* __restrict__ kr,
                            const int*   __restrict__ topk,
                            bf16* __restrict__ aohi, bf16* __restrict__ aolo)
{
    const int warp = (blockIdx.x * blockDim.x + threadIdx.x) >> 5;
    const int lane = threadIdx.x & 31;
    if (warp >= Tn * Hn) return;
    const int t = warp >> 4;
    const int h = warp & (Hn - 1);

    const int idx = topk[t * Kn + lane];

    const float* qp = q + (size_t)t * Dn + h * HDn;
    const float* kp = kmat + (size_t)idx * Dn + h * HDn;
    float s = 0.f;
#pragma unroll
    for (int d = 0; d < HDn; d += 4) {
        float4 qv = *reinterpret_cast<const float4*>(qp + d);
        float4 kv = *reinterpret_cast<const float4*>(kp + d);
        s = fmaf(qv.x, kv.x, s); s = fmaf(qv.y, kv.y, s);
        s = fmaf(qv.z, kv.z, s); s = fmaf(qv.w, kv.w, s);
    }
    const float* qrp = qr + (size_t)t * (Hn * RDn) + h * RDn;
    const float* krp = kr + (size_t)idx * RDn;
#pragma unroll
    for (int d = 0; d < RDn; d += 4) {
        float4 a = *reinterpret_cast<const float4*>(qrp + d);
        float4 b = *reinterpret_cast<const float4*>(krp + d);
        s = fmaf(a.x, b.x, s); s = fmaf(a.y, b.y, s);
        s = fmaf(a.z, b.z, s); s = fmaf(a.w, b.w, s);
    }
    s *= SCALE_ATTN;

    float m = s;
#pragma unroll
    for (int o = 16; o; o >>= 1) m = fmaxf(m, __shfl_xor_sync(0xFFFFFFFFu, m, o));
    float e = expf(s - m);
    float sum = e;
#pragma unroll
    for (int o = 16; o; o >>= 1) sum += __shfl_xor_sync(0xFFFFFFFFu, sum, o);
    float w = e / sum;

    float acc0 = 0.f, acc1 = 0.f, acc2 = 0.f, acc3 = 0.f;
#pragma unroll
    for (int j = 0; j < Kn; j++) {
        float wj = __shfl_sync(0xFFFFFFFFu, w, j);
        int   ij = __shfl_sync(0xFFFFFFFFu, idx, j);
        const float* vp = vmat + (size_t)ij * Dn + h * HDn;
        acc0 = fmaf(wj, vp[lane],      acc0);
        acc1 = fmaf(wj, vp[lane + 32], acc1);
        acc2 = fmaf(wj, vp[lane + 64], acc2);
        acc3 = fmaf(wj, vp[lane + 96], acc3);
    }
    const size_t opofs = (size_t)t * Dn + h * HDn;
    {
        bf16 h0 = __float2bfloat16(acc0);
        bf16 h1 = __float2bfloat16(acc1);
        bf16 h2 = __float2bfloat16(acc2);
        bf16 h3 = __float2bfloat16(acc3);
        aohi[opofs + lane]      = h0;
        aohi[opofs + lane + 32] = h1;
        aohi[opofs + lane + 64] = h2;
        aohi[opofs + lane + 96] = h3;
        aolo[opofs + lane]      = __float2bfloat16(acc0 - __bfloat162float(h0));
        aolo[opofs + lane + 32] = __float2bfloat16(acc1 - __bfloat162float(h1));
        aolo[opofs + lane + 64] = __float2bfloat16(acc2 - __bfloat162float(h2));
        aolo[opofs + lane + 96] = __float2bfloat16(acc3 - __bfloat162float(h3));
    }
}

// ---------------------------------------------------------------------------
// Launcher
// ---------------------------------------------------------------------------
extern "C" void kernel_launch(void* const* d_in, const int* in_sizes, int n_in,
                              void* d_out, int out_size)
{
    const float* x    = (const float*)d_in[0];
    const float* Wqd  = (const float*)d_in[1];
    const float* Wqu  = (const float*)d_in[2];
    const float* Wqr  = (const float*)d_in[3];
    const float* Wkvd = (const float*)d_in[4];
    const float* Wku  = (const float*)d_in[5];
    const float* Wvu  = (const float*)d_in[6];
    const float* Wkr  = (const float*)d_in[7];
    const float* Wo   = (const float*)d_in[8];
    const int*   topk = (const int*)  d_in[9];
    float* out = (float*)d_out;

    float *q, *qr, *k, *v, *kr, *krp;
    cudaGetSymbolAddress((void**)&q,   g_q);
    cudaGetSymbolAddress((void**)&qr,  g_qr);
    cudaGetSymbolAddress((void**)&k,   g_k);
    cudaGetSymbolAddress((void**)&v,   g_v);
    cudaGetSymbolAddress((void**)&kr,  g_kr);
    cudaGetSymbolAddress((void**)&krp, g_krp);

    bf16 *x_hi, *x_lo, *ql_hi, *ql_lo, *ckv_hi, *ckv_lo, *ao_hi, *ao_lo;
    cudaGetSymbolAddress((void**)&x_hi,   g_x_hi);
    cudaGetSymbolAddress((void**)&x_lo,   g_x_lo);
    cudaGetSymbolAddress((void**)&ql_hi,  g_ql_hi);
    cudaGetSymbolAddress((void**)&ql_lo,  g_ql_lo);
    cudaGetSymbolAddress((void**)&ckv_hi, g_ckv_hi);
    cudaGetSymbolAddress((void**)&ckv_lo, g_ckv_lo);
    cudaGetSymbolAddress((void**)&ao_hi,  g_ao_hi);
    cudaGetSymbolAddress((void**)&ao_lo,  g_ao_lo);

    bf16 *WqdT_hi, *WqdT_lo, *WkvdT_hi, *WkvdT_lo, *WquT_hi, *WquT_lo,
         *WqrT_hi, *WqrT_lo, *WkuT_hi, *WkuT_lo, *WvuT_hi, *WvuT_lo,
         *WkrT_hi, *WkrT_lo, *WoT_hi, *WoT_lo;
    cudaGetSymbolAddress((void**)&WqdT_hi,  g_WqdT_hi);
    cudaGetSymbolAddress((void**)&WqdT_lo,  g_WqdT_lo);
    cudaGetSymbolAddress((void**)&WkvdT_hi, g_WkvdT_hi);
    cudaGetSymbolAddress((void**)&WkvdT_lo, g_WkvdT_lo);
    cudaGetSymbolAddress((void**)&WquT_hi,  g_WquT_hi);
    cudaGetSymbolAddress((void**)&WquT_lo,  g_WquT_lo);
    cudaGetSymbolAddress((void**)&WqrT_hi,  g_WqrT_hi);
    cudaGetSymbolAddress((void**)&WqrT_lo,  g_WqrT_lo);
    cudaGetSymbolAddress((void**)&WkuT_hi,  g_WkuT_hi);
    cudaGetSymbolAddress((void**)&WkuT_lo,  g_WkuT_lo);
    cudaGetSymbolAddress((void**)&WvuT_hi,  g_WvuT_hi);
    cudaGetSymbolAddress((void**)&WvuT_lo,  g_WvuT_lo);
    cudaGetSymbolAddress((void**)&WkrT_hi,  g_WkrT_hi);
    cudaGetSymbolAddress((void**)&WkrT_lo,  g_WkrT_lo);
    cudaGetSymbolAddress((void**)&WoT_hi,   g_WoT_hi);
    cudaGetSymbolAddress((void**)&WoT_lo,   g_WoT_lo);

    // 3-stage smem: NT=128 -> 3*64KB = 196608; NT=64 -> 3*48KB = 147456
    constexpr int SMEM3_128 = 3 * (2 * 128 * 128 + 2 * 128 * 128) / 2 * 2 / 2; // keep explicit below
    (void)SMEM3_128;
    constexpr int S128 = 3 * (2 * 128 * 128 + 2 * 128 * 128);  // wrong? compute: stage=65536 -> 196608
    (void)S128;
    const int SMEM_128 = 196608;
    const int SMEM_64  = 147456;
    cudaFuncSetAttribute(mm_down_kernel, cudaFuncAttributeMaxDynamicSharedMemorySize, SMEM_128);
    cudaFuncSetAttribute(mm_up_kernel,   cudaFuncAttributeMaxDynamicSharedMemorySize, SMEM_128);
    cudaFuncSetAttribute(mm_wo_kernel,   cudaFuncAttributeMaxDynamicSharedMemorySize, SMEM_128);
    cudaFuncSetAttribute(mm_kr_kernel,   cudaFuncAttributeMaxDynamicSharedMemorySize, SMEM_64);

    // 1) split x
    split_kernel<<<(Tn * Dn + 255) / 256, 256>>>(x, x_hi, x_lo, Tn * Dn);

    // 2) transpose+split weights: W[K,N] -> Wt[N,K]
    dim3 tb(32, 8);
    tsplit_kernel<<<dim3(Ln / 32,        Dn / 32), tb>>>(Wqd,  WqdT_hi,  WqdT_lo,  Dn, Ln);
    tsplit_kernel<<<dim3(Ln / 32,        Dn / 32), tb>>>(Wkvd, WkvdT_hi, WkvdT_lo, Dn, Ln);
    tsplit_kernel<<<dim3(Dn / 32,        Ln / 32), tb>>>(Wqu,  WquT_hi,  WquT_lo,  Ln, Dn);
    tsplit_kernel<<<dim3(Hn * RDn / 32,  Ln / 32), tb>>>(Wqr,  WqrT_hi,  WqrT_lo,  Ln, Hn * RDn);
    tsplit_kernel<<<dim3(Dn / 32,        Ln / 32), tb>>>(Wku,  WkuT_hi,  WkuT_lo,  Ln, Dn);
    tsplit_kernel<<<dim3(Dn / 32,        Ln / 32), tb>>>(Wvu,  WvuT_hi,  WvuT_lo,  Ln, Dn);
    tsplit_kernel<<<dim3(RDn / 32,       Dn / 32), tb>>>(Wkr,  WkrT_hi,  WkrT_lo,  Dn, RDn);
    tsplit_kernel<<<dim3(Dn / 32,        Dn / 32), tb>>>(Wo,   WoT_hi,   WoT_lo,   Dn, Dn);

    // 3) kr partials (independent of down/up chain; launch early)
    mm_kr_kernel<<<16 * KSPLIT, 256, SMEM_64>>>(x_hi, x_lo, WkrT_hi, WkrT_lo, krp);

    // 4) down-projections (merged; split-bf16 epilogue)
    mm_down_kernel<<<128, 256, SMEM_128>>>(x_hi, x_lo,
                                           WqdT_hi, WqdT_lo, WkvdT_hi, WkvdT_lo,
                                           ql_hi, ql_lo, ckv_hi, ckv_lo);

    // 5) up-projections (merged: q, qr, k, v)
    mm_up_kernel<<<896, 256, SMEM_128>>>(ql_hi, ql_lo, ckv_hi, ckv_lo,
                                         WquT_hi, WquT_lo, WqrT_hi, WqrT_lo,
                                         WkuT_hi, WkuT_lo, WvuT_hi, WvuT_lo,
                                         q, qr, k, v);

    // 6) rope
    rope_qr_kernel<<<(Tn * Hn * 32 + 255) / 256, 256>>>(qr);
    rope_kr_reduce_kernel<<<(Tn * 32 + 255) / 256, 256>>>(krp, kr);

    // 7) sparse attention (emits bf16 hi/lo ao)
    attn_kernel<<<(Tn * Hn * 32 + 255) / 256, 256>>>(q, qr, k, v, kr, topk, ao_hi, ao_lo);

    // 8) output projection
    mm_wo_kernel<<<256, 256, SMEM_128>>>(ao_hi, ao_lo, WoT_hi, WoT_lo, out);
}

// round 5
// speedup vs baseline: 5.7494x; 1.3979x over previous
#include <cuda_runtime.h>
#include <cuda_bf16.h>
#include <math.h>
#include <stdint.h>

// Problem constants
#define Tn   2048
#define Dn   2048
#define Hn   16
#define HDn  128
#define Ln   512
#define RDn  64
#define Kn   32
#define KSPLIT 8
#define SCALE_ATTN (0.07216878364870323f)  // 1/sqrt(192)

typedef __nv_bfloat16 bf16;

// ---------------------------------------------------------------------------
// Scratch (static device globals)
// ---------------------------------------------------------------------------
__device__ float g_q  [Tn * Dn];
__device__ float g_qr [Tn * Hn * RDn];
__device__ float g_k  [Tn * Dn];
__device__ float g_v  [Tn * Dn];
__device__ float g_kr [Tn * RDn];
__device__ float g_krp[KSPLIT * Tn * RDn];   // kr split-K partials

__device__ bf16 g_x_hi  [Tn * Dn],  g_x_lo  [Tn * Dn];
__device__ bf16 g_ql_hi [Tn * Ln],  g_ql_lo [Tn * Ln];
__device__ bf16 g_ckv_hi[Tn * Ln],  g_ckv_lo[Tn * Ln];
__device__ bf16 g_ao_hi [Tn * Dn],  g_ao_lo [Tn * Dn];

__device__ bf16 g_WqdT_hi [Ln * Dn],        g_WqdT_lo [Ln * Dn];
__device__ bf16 g_WkvdT_hi[Ln * Dn],        g_WkvdT_lo[Ln * Dn];
__device__ bf16 g_WquT_hi [Dn * Ln],        g_WquT_lo [Dn * Ln];
__device__ bf16 g_WqrT_hi [Hn * RDn * Ln],  g_WqrT_lo [Hn * RDn * Ln];
__device__ bf16 g_WkuT_hi [Dn * Ln],        g_WkuT_lo [Dn * Ln];
__device__ bf16 g_WvuT_hi [Dn * Ln],        g_WvuT_lo [Dn * Ln];
__device__ bf16 g_WkrT_hi [RDn * Dn],       g_WkrT_lo [RDn * Dn];
__device__ bf16 g_WoT_hi  [Dn * Dn],        g_WoT_lo  [Dn * Dn];

// ---------------------------------------------------------------------------
// Low-level helpers (plain sm_80-era PTX only — no 'a'-suffix features)
// ---------------------------------------------------------------------------
__device__ __forceinline__ uint32_t smem_u32_of(const void* p) {
    uint32_t a;
    asm("{ .reg .u64 t; cvta.to.shared.u64 t, %1; cvt.u32.u64 %0, t; }"
        : "=r"(a) : "l"(p));
    return a;
}

__device__ __forceinline__ void cp16(uint32_t saddr, const void* gptr) {
    asm volatile("cp.async.cg.shared.global [%0], [%1], 16;"
                 :: "r"(saddr), "l"(gptr));
}
#define CP_COMMIT() asm volatile("cp.async.commit_group;" ::: "memory")
#define CP_WAIT0()  asm volatile("cp.async.wait_group 0;" ::: "memory")
#define CP_WAIT1()  asm volatile("cp.async.wait_group 1;" ::: "memory")

__device__ __forceinline__ void ldm_x4(uint32_t* r, uint32_t addr) {
    asm volatile("ldmatrix.sync.aligned.m8n8.x4.shared.b16 {%0,%1,%2,%3}, [%4];"
                 : "=r"(r[0]), "=r"(r[1]), "=r"(r[2]), "=r"(r[3]) : "r"(addr));
}

__device__ __forceinline__ void mma_bf16(float* d, const uint32_t* a, const uint32_t* b) {
    asm volatile("mma.sync.aligned.m16n8k16.row.col.f32.bf16.bf16.f32 "
                 "{%0,%1,%2,%3}, {%4,%5,%6,%7}, {%8,%9}, {%0,%1,%2,%3};"
                 : "+f"(d[0]), "+f"(d[1]), "+f"(d[2]), "+f"(d[3])
                 : "r"(a[0]), "r"(a[1]), "r"(a[2]), "r"(a[3]),
                   "r"(b[0]), "r"(b[1]));
}

// ---------------------------------------------------------------------------
// Core split-bf16 mma.sync GEMM tile (same engine as R4)
// EPI: 0 = fp32 store; 1 = bf16 hi/lo split store.
// ---------------------------------------------------------------------------
template<int NT, int EPI>
__device__ __forceinline__ void mm_core(
    const bf16* __restrict__ Ahi, const bf16* __restrict__ Alo,
    const bf16* __restrict__ Bhi, const bf16* __restrict__ Blo,
    float* __restrict__ C, bf16* __restrict__ Chi, bf16* __restrict__ Clo,
    int Kd, int Ntot, int m0, int n0, int kbase, int nch, uint8_t* smem)
{
    constexpr int ABYTES = 128 * 128;
    constexpr int BBYTES = NT * 128;
    constexpr int STAGE  = 2 * ABYTES + 2 * BBYTES;
    constexpr int MI = (NT == 128) ? 4 : 2;
    constexpr int NI = 4;

    const uint32_t sm32 = smem_u32_of(smem);
    const int tid  = threadIdx.x;
    const int wid  = tid >> 5;
    const int lane = tid & 31;

    const int mwarp = (NT == 128) ? ((wid & 1) * 64) : ((wid & 3) * 32);
    const int nwarp = (NT == 128) ? ((wid >> 1) * 32) : ((wid >> 2) * 32);

    const int lchunk = tid & 7;
    const int lrow   = tid >> 3;

    float acc[MI][NI][4];
#pragma unroll
    for (int i = 0; i < MI; i++)
#pragma unroll
        for (int j = 0; j < NI; j++)
#pragma unroll
            for (int r = 0; r < 4; r++) acc[i][j][r] = 0.f;

    auto load_chunk = [&](int c, int s) {
        const uint32_t base = sm32 + s * STAGE;
        const size_t kofs = (size_t)kbase + (size_t)c * 64 + lchunk * 8;
#pragma unroll
        for (int r = 0; r < 128; r += 32) {
            const int row = lrow + r;
            const size_t go = (size_t)(m0 + row) * Kd + kofs;
            const uint32_t so = base + row * 128 + ((lchunk ^ (row & 7)) << 4);
            cp16(so,          Ahi + go);
            cp16(so + ABYTES, Alo + go);
        }
#pragma unroll
        for (int r = 0; r < NT; r += 32) {
            const int row = lrow + r;
            const size_t go = (size_t)(n0 + row) * Kd + kofs;
            const uint32_t so = base + 2 * ABYTES + row * 128 + ((lchunk ^ (row & 7)) << 4);
            cp16(so,          Bhi + go);
            cp16(so + BBYTES, Blo + go);
        }
        CP_COMMIT();
    };

    auto compute_chunk = [&](int s) {
        const uint32_t aBase = sm32 + s * STAGE;
        const uint32_t bBase = aBase + 2 * ABYTES;
#pragma unroll
        for (int ks = 0; ks < 4; ks++) {
            uint32_t aHi[MI][4], aLo[MI][4], bHi[NI][2], bLo[NI][2];
#pragma unroll
            for (int mi = 0; mi < MI; mi++) {
                const int row = mwarp + mi * 16 + (lane & 15);
                const int chunk = ks * 2 + (lane >> 4);
                const uint32_t off = row * 128 + ((chunk ^ (row & 7)) << 4);
                ldm_x4(aHi[mi], aBase + off);
                ldm_x4(aLo[mi], aBase + ABYTES + off);
            }
#pragma unroll
            for (int nj = 0; nj < NI / 2; nj++) {
                const int row = nwarp + nj * 16 + ((lane >> 4) << 3) + (lane & 7);
                const int chunk = ks * 2 + ((lane >> 3) & 1);
                const uint32_t off = row * 128 + ((chunk ^ (row & 7)) << 4);
                uint32_t r4[4];
                ldm_x4(r4, bBase + off);
                bHi[nj * 2][0] = r4[0]; bHi[nj * 2][1] = r4[1];
                bHi[nj * 2 + 1][0] = r4[2]; bHi[nj * 2 + 1][1] = r4[3];
                ldm_x4(r4, bBase + BBYTES + off);
                bLo[nj * 2][0] = r4[0]; bLo[nj * 2][1] = r4[1];
                bLo[nj * 2 + 1][0] = r4[2]; bLo[nj * 2 + 1][1] = r4[3];
            }
#pragma unroll
            for (int mi = 0; mi < MI; mi++)
#pragma unroll
                for (int ni = 0; ni < NI; ni++) {
                    mma_bf16(acc[mi][ni], aHi[mi], bHi[ni]);
                    mma_bf16(acc[mi][ni], aHi[mi], bLo[ni]);
                    mma_bf16(acc[mi][ni], aLo[mi], bHi[ni]);
                }
        }
    };

    load_chunk(0, 0);
    if (nch > 1) load_chunk(1, 1);
    for (int c = 0; c < nch; c++) {
        if (c + 1 < nch) { CP_WAIT1(); } else { CP_WAIT0(); }
        __syncthreads();
        if (c + 2 < nch) load_chunk(c + 2, (c + 2) % 3);
        compute_chunk(c % 3);
    }

#pragma unroll
    for (int mi = 0; mi < MI; mi++)
#pragma unroll
        for (int ni = 0; ni < NI; ni++) {
            const int row = m0 + mwarp + mi * 16 + (lane >> 2);
            const int col = n0 + nwarp + ni * 8 + ((lane & 3) << 1);
            if (EPI == 1) {
                float f0 = acc[mi][ni][0], f1 = acc[mi][ni][1];
                float f2 = acc[mi][ni][2], f3 = acc[mi][ni][3];
                bf16 h0 = __float2bfloat16(f0), h1 = __float2bfloat16(f1);
                bf16 h2 = __float2bfloat16(f2), h3 = __float2bfloat16(f3);
                bf16 l0 = __float2bfloat16(f0 - __bfloat162float(h0));
                bf16 l1 = __float2bfloat16(f1 - __bfloat162float(h1));
                bf16 l2 = __float2bfloat16(f2 - __bfloat162float(h2));
                bf16 l3 = __float2bfloat16(f3 - __bfloat162float(h3));
                *reinterpret_cast<__nv_bfloat162*>(Chi + (size_t)row * Ntot + col) =
                    __halves2bfloat162(h0, h1);
                *reinterpret_cast<__nv_bfloat162*>(Clo + (size_t)row * Ntot + col) =
                    __halves2bfloat162(l0, l1);
                *reinterpret_cast<__nv_bfloat162*>(Chi + (size_t)(row + 8) * Ntot + col) =
                    __halves2bfloat162(h2, h3);
                *reinterpret_cast<__nv_bfloat162*>(Clo + (size_t)(row + 8) * Ntot + col) =
                    __halves2bfloat162(l2, l3);
            } else {
                *reinterpret_cast<float2*>(C + (size_t)row * Ntot + col) =
                    make_float2(acc[mi][ni][0], acc[mi][ni][1]);
                *reinterpret_cast<float2*>(C + (size_t)(row + 8) * Ntot + col) =
                    make_float2(acc[mi][ni][2], acc[mi][ni][3]);
            }
        }
}

// ---------------------------------------------------------------------------
// GEMM wrapper kernels
// ---------------------------------------------------------------------------
__global__ __launch_bounds__(256, 1)
void mm_down_kernel(const bf16* __restrict__ xhi, const bf16* __restrict__ xlo,
                    const bf16* __restrict__ Bqhi, const bf16* __restrict__ Bqlo,
                    const bf16* __restrict__ Bkhi, const bf16* __restrict__ Bklo,
                    bf16* __restrict__ qlhi, bf16* __restrict__ qllo,
                    bf16* __restrict__ ckvhi, bf16* __restrict__ ckvlo)
{
    extern __shared__ __align__(1024) uint8_t smem[];
    const int bx = blockIdx.x;
    const int seg = bx >> 6;
    const int b = bx & 63;
    const int m0 = (b & 15) * 128;
    const int n0 = (b >> 4) * 128;
    if (seg == 0)
        mm_core<128, 1>(xhi, xlo, Bqhi, Bqlo, nullptr, qlhi, qllo,
                        Dn, Ln, m0, n0, 0, 32, smem);
    else
        mm_core<128, 1>(xhi, xlo, Bkhi, Bklo, nullptr, ckvhi, ckvlo,
                        Dn, Ln, m0, n0, 0, 32, smem);
}

__global__ __launch_bounds__(256, 1)
void mm_up_kernel(const bf16* __restrict__ qlhi, const bf16* __restrict__ qllo,
                  const bf16* __restrict__ ckvhi, const bf16* __restrict__ ckvlo,
                  const bf16* __restrict__ Wquhi, const bf16* __restrict__ Wqulo,
                  const bf16* __restrict__ Wqrhi, const bf16* __restrict__ Wqrlo,
                  const bf16* __restrict__ Wkuhi, const bf16* __restrict__ Wkulo,
                  const bf16* __restrict__ Wvuhi, const bf16* __restrict__ Wvulo,
                  float* __restrict__ q, float* __restrict__ qr,
                  float* __restrict__ k, float* __restrict__ v)
{
    extern __shared__ __align__(1024) uint8_t smem[];
    const int bx = blockIdx.x;
    if (bx < 256) {
        mm_core<128, 0>(qlhi, qllo, Wquhi, Wqulo, q, nullptr, nullptr,
                        Ln, Dn, (bx & 15) * 128, (bx >> 4) * 128, 0, 8, smem);
    } else if (bx < 384) {
        const int b = bx - 256;
        mm_core<128, 0>(qlhi, qllo, Wqrhi, Wqrlo, qr, nullptr, nullptr,
                        Ln, Hn * RDn, (b & 15) * 128, (b >> 4) * 128, 0, 8, smem);
    } else if (bx < 640) {
        const int b = bx - 384;
        mm_core<128, 0>(ckvhi, ckvlo, Wkuhi, Wkulo, k, nullptr, nullptr,
                        Ln, Dn, (b & 15) * 128, (b >> 4) * 128, 0, 8, smem);
    } else {
        const int b = bx - 640;
        mm_core<128, 0>(ckvhi, ckvlo, Wvuhi, Wvulo, v, nullptr, nullptr,
                        Ln, Dn, (b & 15) * 128, (b >> 4) * 128, 0, 8, smem);
    }
}

__global__ __launch_bounds__(256, 1)
void mm_kr_kernel(const bf16* __restrict__ xhi, const bf16* __restrict__ xlo,
                  const bf16* __restrict__ Bhi, const bf16* __restrict__ Blo,
                  float* __restrict__ krp)
{
    extern __shared__ __align__(1024) uint8_t smem[];
    const int bx = blockIdx.x;
    const int mt = bx & 15;
    const int ks = bx >> 4;
    mm_core<64, 0>(xhi, xlo, Bhi, Blo, krp + (size_t)ks * Tn * RDn,
                   nullptr, nullptr,
                   Dn, RDn, mt * 128, 0, ks * (Dn / KSPLIT), (Dn / KSPLIT) / 64, smem);
}

__global__ __launch_bounds__(256, 1)
void mm_wo_kernel(const bf16* __restrict__ aohi, const bf16* __restrict__ aolo,
                  const bf16* __restrict__ Bhi, const bf16* __restrict__ Blo,
                  float* __restrict__ out)
{
    extern __shared__ __align__(1024) uint8_t smem[];
    const int bx = blockIdx.x;
    mm_core<128, 0>(aohi, aolo, Bhi, Blo, out, nullptr, nullptr,
                    Dn, Dn, (bx & 15) * 128, (bx >> 4) * 128, 0, 32, smem);
}

// ---------------------------------------------------------------------------
// Merged preprocessing: x split (vectorized) + 8 weight transpose-splits.
// Block = 256 threads.
//   blocks [0, 2048):      x split, 2048 floats per block (float4 IO)
//   blocks [2048, 11904):  tsplit segments, one 32x32 tile per block
// ---------------------------------------------------------------------------
__device__ __forceinline__ void tsplit_tile(
    const float* __restrict__ W, bf16* __restrict__ hi, bf16* __restrict__ lo,
    int Kd, int N, int bx, int by)
{
    __shared__ float tile[32][33];
    const int n0 = bx * 32, k0 = by * 32;
    const int tx = threadIdx.x & 31;
    const int ty = threadIdx.x >> 5;
#pragma unroll
    for (int i = 0; i < 32; i += 8)
        tile[ty + i][tx] = W[(size_t)(k0 + ty + i) * N + n0 + tx];
    __syncthreads();
#pragma unroll
    for (int i = 0; i < 32; i += 8) {
        float f = tile[tx][ty + i];
        bf16 h = __float2bfloat16(f);
        size_t o = (size_t)(n0 + ty + i) * Kd + k0 + tx;
        hi[o] = h;
        lo[o] = __float2bfloat16(f - __bfloat162float(h));
    }
}

__global__ __launch_bounds__(256)
void prep_kernel(const float* __restrict__ x,
                 const float* __restrict__ Wqd,  const float* __restrict__ Wqu,
                 const float* __restrict__ Wqr,  const float* __restrict__ Wkvd,
                 const float* __restrict__ Wku,  const float* __restrict__ Wvu,
                 const float* __restrict__ Wkr,  const float* __restrict__ Wo,
                 bf16* __restrict__ xhi, bf16* __restrict__ xlo,
                 bf16* __restrict__ WqdThi,  bf16* __restrict__ WqdTlo,
                 bf16* __restrict__ WkvdThi, bf16* __restrict__ WkvdTlo,
                 bf16* __restrict__ WquThi,  bf16* __restrict__ WquTlo,
                 bf16* __restrict__ WqrThi,  bf16* __restrict__ WqrTlo,
                 bf16* __restrict__ WkuThi,  bf16* __restrict__ WkuTlo,
                 bf16* __restrict__ WvuThi,  bf16* __restrict__ WvuTlo,
                 bf16* __restrict__ WkrThi,  bf16* __restrict__ WkrTlo,
                 bf16* __restrict__ WoThi,   bf16* __restrict__ WoTlo)
{
    const int b = blockIdx.x;
    if (b < 2048) {
        // x split: 2048 floats per block, float4 in, 4xbf16 (uint2) out
        const int base = b * 2048 + threadIdx.x * 4;
#pragma unroll
        for (int rep = 0; rep < 2; rep++) {
            const int i = base + rep * 1024;
            float4 f = *reinterpret_cast<const float4*>(x + i);
            bf16 h0 = __float2bfloat16(f.x), h1 = __float2bfloat16(f.y);
            bf16 h2 = __float2bfloat16(f.z), h3 = __float2bfloat16(f.w);
            __nv_bfloat162 hA = __halves2bfloat162(h0, h1);
            __nv_bfloat162 hB = __halves2bfloat162(h2, h3);
            __nv_bfloat162 lA = __halves2bfloat162(
                __float2bfloat16(f.x - __bfloat162float(h0)),
                __float2bfloat16(f.y - __bfloat162float(h1)));
            __nv_bfloat162 lB = __halves2bfloat162(
                __float2bfloat16(f.z - __bfloat162float(h2)),
                __float2bfloat16(f.w - __bfloat162float(h3)));
            *reinterpret_cast<__nv_bfloat162*>(xhi + i)     = hA;
            *reinterpret_cast<__nv_bfloat162*>(xhi + i + 2) = hB;
            *reinterpret_cast<__nv_bfloat162*>(xlo + i)     = lA;
            *reinterpret_cast<__nv_bfloat162*>(xlo + i + 2) = lB;
        }
        return;
    }
    int rb = b - 2048;
    if (rb < 1024)      { tsplit_tile(Wqd,  WqdThi,  WqdTlo,  Dn, Ln,      rb & 15, rb >> 4); return; }
    rb -= 1024;
    if (rb < 1024)      { tsplit_tile(Wkvd, WkvdThi, WkvdTlo, Dn, Ln,      rb & 15, rb >> 4); return; }
    rb -= 1024;
    if (rb < 1024)      { tsplit_tile(Wqu,  WquThi,  WquTlo,  Ln, Dn,      rb & 63, rb >> 6); return; }
    rb -= 1024;
    if (rb < 512)       { tsplit_tile(Wqr,  WqrThi,  WqrTlo,  Ln, Hn*RDn,  rb & 31, rb >> 5); return; }
    rb -= 512;
    if (rb < 1024)      { tsplit_tile(Wku,  WkuThi,  WkuTlo,  Ln, Dn,      rb & 63, rb >> 6); return; }
    rb -= 1024;
    if (rb < 1024)      { tsplit_tile(Wvu,  WvuThi,  WvuTlo,  Ln, Dn,      rb & 63, rb >> 6); return; }
    rb -= 1024;
    if (rb < 128)       { tsplit_tile(Wkr,  WkrThi,  WkrTlo,  Dn, RDn,     rb & 1,  rb >> 1); return; }
    rb -= 128;
    /* Wo: 4096 */      { tsplit_tile(Wo,   WoThi,   WoTlo,   Dn, Dn,      rb & 63, rb >> 6); }
}

// ---------------------------------------------------------------------------
// Merged RoPE: qr in-place + kr split-K reduce + rope
// ---------------------------------------------------------------------------
__global__ void rope_kernel(float* __restrict__ qr,
                            const float* __restrict__ krp,
                            float* __restrict__ kr)
{
    int i = blockIdx.x * blockDim.x + threadIdx.x;
    if (i < Tn * Hn * 32) {
        int r = i & 31;
        int h = (i >> 5) & (Hn - 1);
        int t = i >> 9;
        float f = powf(10000.0f, -(float)r / 32.0f);
        float ang = (float)t * f;
        float c = cosf(ang), s = sinf(ang);
        int base = t * (Hn * RDn) + h * RDn + r;
        float a = qr[base];
        float bv = qr[base + 32];
        qr[base]      = a * c - bv * s;
        qr[base + 32] = bv * c + a * s;
        return;
    }
    i -= Tn * Hn * 32;
    if (i >= Tn * 32) return;
    int r = i & 31;
    int t = i >> 5;
    float a = 0.f, bv = 0.f;
#pragma unroll
    for (int s = 0; s < KSPLIT; s++) {
        a  += krp[(size_t)s * Tn * RDn + t * RDn + r];
        bv += krp[(size_t)s * Tn * RDn + t * RDn + r + 32];
    }
    float f = powf(10000.0f, -(float)r / 32.0f);
    float ang = (float)t * f;
    float c = cosf(ang), sn = sinf(ang);
    kr[t * RDn + r]      = a * c - bv * sn;
    kr[t * RDn + r + 32] = bv * c + a * sn;
}

// ---------------------------------------------------------------------------
// Sparse top-k attention, v2: cooperative row gather (full sector efficiency).
// One warp per (t, h). For each selected token j, ALL lanes cooperatively
// load contiguous 512B of K row + 256B of kr row, partial-dot, warp-reduce.
// ---------------------------------------------------------------------------
__global__ void attn_kernel(const float* __restrict__ q,
                            const float* __restrict__ qr,
                            const float* __restrict__ kmat,
                            const float* __restrict__ vmat,
                            const float* __restrict__ kr,
                            const int*   __restrict__ topk,
                            bf16* __restrict__ aohi, bf16* __restrict__ aolo)
{
    const int warp = (blockIdx.x * blockDim.x + threadIdx.x) >> 5;
    const int lane = threadIdx.x & 31;
    if (warp >= Tn * Hn) return;
    const int t = warp >> 4;
    const int h = warp & (Hn - 1);

    const int idx = topk[t * Kn + lane];

    // my slice of q (4 elems) and qr (2 elems) — reused across all j
    const float4 qv = *reinterpret_cast<const float4*>(
        q + (size_t)t * Dn + h * HDn + lane * 4);
    const float2 qrv = *reinterpret_cast<const float2*>(
        qr + (size_t)t * (Hn * RDn) + h * RDn + lane * 2);

    float s = 0.f;
#pragma unroll
    for (int j = 0; j < Kn; j++) {
        const int ij = __shfl_sync(0xFFFFFFFFu, idx, j);
        const float4 kv = *reinterpret_cast<const float4*>(
            kmat + (size_t)ij * Dn + h * HDn + lane * 4);
        const float2 krv = *reinterpret_cast<const float2*>(
            kr + (size_t)ij * RDn + lane * 2);
        float p = qv.x * kv.x + qv.y * kv.y + qv.z * kv.z + qv.w * kv.w
                + qrv.x * krv.x + qrv.y * krv.y;
#pragma unroll
        for (int o = 16; o; o >>= 1) p += __shfl_xor_sync(0xFFFFFFFFu, p, o);
        if (lane == j) s = p;
    }
    s *= SCALE_ATTN;

    // warp softmax over the 32 per-lane scores
    float m = s;
#pragma unroll
    for (int o = 16; o; o >>= 1) m = fmaxf(m, __shfl_xor_sync(0xFFFFFFFFu, m, o));
    float e = expf(s - m);
    float sum = e;
#pragma unroll
    for (int o = 16; o; o >>= 1) sum += __shfl_xor_sync(0xFFFFFFFFu, sum, o);
    float w = e / sum;

    // weighted V sum (fp32, coalesced)
    float acc0 = 0.f, acc1 = 0.f, acc2 = 0.f, acc3 = 0.f;
#pragma unroll
    for (int j = 0; j < Kn; j++) {
        float wj = __shfl_sync(0xFFFFFFFFu, w, j);
        int   ij = __shfl_sync(0xFFFFFFFFu, idx, j);
        const float* vp = vmat + (size_t)ij * Dn + h * HDn;
        acc0 = fmaf(wj, vp[lane],      acc0);
        acc1 = fmaf(wj, vp[lane + 32], acc1);
        acc2 = fmaf(wj, vp[lane + 64], acc2);
        acc3 = fmaf(wj, vp[lane + 96], acc3);
    }
    const size_t opofs = (size_t)t * Dn + h * HDn;
    {
        bf16 h0 = __float2bfloat16(acc0);
        bf16 h1 = __float2bfloat16(acc1);
        bf16 h2 = __float2bfloat16(acc2);
        bf16 h3 = __float2bfloat16(acc3);
        aohi[opofs + lane]      = h0;
        aohi[opofs + lane + 32] = h1;
        aohi[opofs + lane + 64] = h2;
        aohi[opofs + lane + 96] = h3;
        aolo[opofs + lane]      = __float2bfloat16(acc0 - __bfloat162float(h0));
        aolo[opofs + lane + 32] = __float2bfloat16(acc1 - __bfloat162float(h1));
        aolo[opofs + lane + 64] = __float2bfloat16(acc2 - __bfloat162float(h2));
        aolo[opofs + lane + 96] = __float2bfloat16(acc3 - __bfloat162float(h3));
    }
}

// ---------------------------------------------------------------------------
// Launcher
// ---------------------------------------------------------------------------
extern "C" void kernel_launch(void* const* d_in, const int* in_sizes, int n_in,
                              void* d_out, int out_size)
{
    const float* x    = (const float*)d_in[0];
    const float* Wqd  = (const float*)d_in[1];
    const float* Wqu  = (const float*)d_in[2];
    const float* Wqr  = (const float*)d_in[3];
    const float* Wkvd = (const float*)d_in[4];
    const float* Wku  = (const float*)d_in[5];
    const float* Wvu  = (const float*)d_in[6];
    const float* Wkr  = (const float*)d_in[7];
    const float* Wo   = (const float*)d_in[8];
    const int*   topk = (const int*)  d_in[9];
    float* out = (float*)d_out;

    float *q, *qr, *k, *v, *kr, *krp;
    cudaGetSymbolAddress((void**)&q,   g_q);
    cudaGetSymbolAddress((void**)&qr,  g_qr);
    cudaGetSymbolAddress((void**)&k,   g_k);
    cudaGetSymbolAddress((void**)&v,   g_v);
    cudaGetSymbolAddress((void**)&kr,  g_kr);
    cudaGetSymbolAddress((void**)&krp, g_krp);

    bf16 *x_hi, *x_lo, *ql_hi, *ql_lo, *ckv_hi, *ckv_lo, *ao_hi, *ao_lo;
    cudaGetSymbolAddress((void**)&x_hi,   g_x_hi);
    cudaGetSymbolAddress((void**)&x_lo,   g_x_lo);
    cudaGetSymbolAddress((void**)&ql_hi,  g_ql_hi);
    cudaGetSymbolAddress((void**)&ql_lo,  g_ql_lo);
    cudaGetSymbolAddress((void**)&ckv_hi, g_ckv_hi);
    cudaGetSymbolAddress((void**)&ckv_lo, g_ckv_lo);
    cudaGetSymbolAddress((void**)&ao_hi,  g_ao_hi);
    cudaGetSymbolAddress((void**)&ao_lo,  g_ao_lo);

    bf16 *WqdT_hi, *WqdT_lo, *WkvdT_hi, *WkvdT_lo, *WquT_hi, *WquT_lo,
         *WqrT_hi, *WqrT_lo, *WkuT_hi, *WkuT_lo, *WvuT_hi, *WvuT_lo,
         *WkrT_hi, *WkrT_lo, *WoT_hi, *WoT_lo;
    cudaGetSymbolAddress((void**)&WqdT_hi,  g_WqdT_hi);
    cudaGetSymbolAddress((void**)&WqdT_lo,  g_WqdT_lo);
    cudaGetSymbolAddress((void**)&WkvdT_hi, g_WkvdT_hi);
    cudaGetSymbolAddress((void**)&WkvdT_lo, g_WkvdT_lo);
    cudaGetSymbolAddress((void**)&WquT_hi,  g_WquT_hi);
    cudaGetSymbolAddress((void**)&WquT_lo,  g_WquT_lo);
    cudaGetSymbolAddress((void**)&WqrT_hi,  g_WqrT_hi);
    cudaGetSymbolAddress((void**)&WqrT_lo,  g_WqrT_lo);
    cudaGetSymbolAddress((void**)&WkuT_hi,  g_WkuT_hi);
    cudaGetSymbolAddress((void**)&WkuT_lo,  g_WkuT_lo);
    cudaGetSymbolAddress((void**)&WvuT_hi,  g_WvuT_hi);
    cudaGetSymbolAddress((void**)&WvuT_lo,  g_WvuT_lo);
    cudaGetSymbolAddress((void**)&WkrT_hi,  g_WkrT_hi);
    cudaGetSymbolAddress((void**)&WkrT_lo,  g_WkrT_lo);
    cudaGetSymbolAddress((void**)&WoT_hi,   g_WoT_hi);
    cudaGetSymbolAddress((void**)&WoT_lo,   g_WoT_lo);

    const int SMEM_128 = 196608;   // 3 stages x 64KB
    const int SMEM_64  = 147456;   // 3 stages x 48KB
    cudaFuncSetAttribute(mm_down_kernel, cudaFuncAttributeMaxDynamicSharedMemorySize, SMEM_128);
    cudaFuncSetAttribute(mm_up_kernel,   cudaFuncAttributeMaxDynamicSharedMemorySize, SMEM_128);
    cudaFuncSetAttribute(mm_wo_kernel,   cudaFuncAttributeMaxDynamicSharedMemorySize, SMEM_128);
    cudaFuncSetAttribute(mm_kr_kernel,   cudaFuncAttributeMaxDynamicSharedMemorySize, SMEM_64);

    // 1) merged preprocessing (x split + all weight transpose-splits)
    prep_kernel<<<11904, 256>>>(x, Wqd, Wqu, Wqr, Wkvd, Wku, Wvu, Wkr, Wo,
                                x_hi, x_lo,
                                WqdT_hi, WqdT_lo, WkvdT_hi, WkvdT_lo,
                                WquT_hi, WquT_lo, WqrT_hi, WqrT_lo,
                                WkuT_hi, WkuT_lo, WvuT_hi, WvuT_lo,
                                WkrT_hi, WkrT_lo, WoT_hi, WoT_lo);

    // 2) kr partials (split-K x 8)
    mm_kr_kernel<<<16 * KSPLIT, 256, SMEM_64>>>(x_hi, x_lo, WkrT_hi, WkrT_lo, krp);

    // 3) down-projections (merged)
    mm_down_kernel<<<128, 256, SMEM_128>>>(x_hi, x_lo,
                                           WqdT_hi, WqdT_lo, WkvdT_hi, WkvdT_lo,
                                           ql_hi, ql_lo, ckv_hi, ckv_lo);

    // 4) up-projections (merged: q, qr, k, v)
    mm_up_kernel<<<896, 256, SMEM_128>>>(ql_hi, ql_lo, ckv_hi, ckv_lo,
                                         WquT_hi, WquT_lo, WqrT_hi, WqrT_lo,
                                         WkuT_hi, WkuT_lo, WvuT_hi, WvuT_lo,
                                         q, qr, k, v);

    // 5) merged rope (qr in-place + kr reduce)
    rope_kernel<<<(Tn * Hn * 32 + Tn * 32 + 255) / 256, 256>>>(qr, krp, kr);

    // 6) sparse attention (cooperative gather, emits bf16 hi/lo ao)
    attn_kernel<<<(Tn * Hn * 32 + 255) / 256, 256>>>(q, qr, k, v, kr, topk, ao_hi, ao_lo);

    // 7) output projection
    mm_wo_kernel<<<256, 256, SMEM_128>>>(ao_hi, ao_lo, WoT_hi, WoT_lo, out);
}

// round 6
// speedup vs baseline: 5.7798x; 1.0053x over previous
#include <cuda_runtime.h>
#include <cuda_bf16.h>
#include <math.h>
#include <stdint.h>

// Problem constants
#define Tn   2048
#define Dn   2048
#define Hn   16
#define HDn  128
#define Ln   512
#define RDn  64
#define Kn   32
#define KSPLIT 8
#define SCALE_ATTN (0.07216878364870323f)  // 1/sqrt(192)

typedef __nv_bfloat16 bf16;

// ---------------------------------------------------------------------------
// Scratch (static device globals)
// ---------------------------------------------------------------------------
__device__ float g_q  [Tn * Dn];
__device__ float g_qr [Tn * Hn * RDn];
__device__ float g_k  [Tn * Dn];
__device__ float g_v  [Tn * Dn];
__device__ float g_kr [Tn * RDn];
__device__ float g_krp[KSPLIT * Tn * RDn];   // kr split-K partials

__device__ bf16 g_x_hi  [Tn * Dn],  g_x_lo  [Tn * Dn];
__device__ bf16 g_ql_hi [Tn * Ln],  g_ql_lo [Tn * Ln];
__device__ bf16 g_ckv_hi[Tn * Ln],  g_ckv_lo[Tn * Ln];
__device__ bf16 g_ao_hi [Tn * Dn],  g_ao_lo [Tn * Dn];

__device__ bf16 g_WqdT_hi [Ln * Dn],        g_WqdT_lo [Ln * Dn];
__device__ bf16 g_WkvdT_hi[Ln * Dn],        g_WkvdT_lo[Ln * Dn];
__device__ bf16 g_WquT_hi [Dn * Ln],        g_WquT_lo [Dn * Ln];
__device__ bf16 g_WqrT_hi [Hn * RDn * Ln],  g_WqrT_lo [Hn * RDn * Ln];
__device__ bf16 g_WkuT_hi [Dn * Ln],        g_WkuT_lo [Dn * Ln];
__device__ bf16 g_WvuT_hi [Dn * Ln],        g_WvuT_lo [Dn * Ln];
__device__ bf16 g_WkrT_hi [RDn * Dn],       g_WkrT_lo [RDn * Dn];
__device__ bf16 g_WoT_hi  [Dn * Dn],        g_WoT_lo  [Dn * Dn];

// ---------------------------------------------------------------------------
// Low-level helpers (plain sm_80-era PTX only — no 'a'-suffix features)
// ---------------------------------------------------------------------------
__device__ __forceinline__ uint32_t smem_u32_of(const void* p) {
    uint32_t a;
    asm("{ .reg .u64 t; cvta.to.shared.u64 t, %1; cvt.u32.u64 %0, t; }"
        : "=r"(a) : "l"(p));
    return a;
}

__device__ __forceinline__ void cp16(uint32_t saddr, const void* gptr) {
    asm volatile("cp.async.cg.shared.global [%0], [%1], 16;"
                 :: "r"(saddr), "l"(gptr));
}
#define CP_COMMIT() asm volatile("cp.async.commit_group;" ::: "memory")
#define CP_WAIT0()  asm volatile("cp.async.wait_group 0;" ::: "memory")
#define CP_WAIT1()  asm volatile("cp.async.wait_group 1;" ::: "memory")

__device__ __forceinline__ void ldm_x4(uint32_t* r, uint32_t addr) {
    asm volatile("ldmatrix.sync.aligned.m8n8.x4.shared.b16 {%0,%1,%2,%3}, [%4];"
                 : "=r"(r[0]), "=r"(r[1]), "=r"(r[2]), "=r"(r[3]) : "r"(addr));
}

__device__ __forceinline__ void mma_bf16(float* d, const uint32_t* a, const uint32_t* b) {
    asm volatile("mma.sync.aligned.m16n8k16.row.col.f32.bf16.bf16.f32 "
                 "{%0,%1,%2,%3}, {%4,%5,%6,%7}, {%8,%9}, {%0,%1,%2,%3};"
                 : "+f"(d[0]), "+f"(d[1]), "+f"(d[2]), "+f"(d[3])
                 : "r"(a[0]), "r"(a[1]), "r"(a[2]), "r"(a[3]),
                   "r"(b[0]), "r"(b[1]));
}

// ---------------------------------------------------------------------------
// Core split-bf16 mma.sync GEMM tile (same engine as R4)
// EPI: 0 = fp32 store; 1 = bf16 hi/lo split store.
// ---------------------------------------------------------------------------
template<int NT, int EPI>
__device__ __forceinline__ void mm_core(
    const bf16* __restrict__ Ahi, const bf16* __restrict__ Alo,
    const bf16* __restrict__ Bhi, const bf16* __restrict__ Blo,
    float* __restrict__ C, bf16* __restrict__ Chi, bf16* __restrict__ Clo,
    int Kd, int Ntot, int m0, int n0, int kbase, int nch, uint8_t* smem)
{
    constexpr int ABYTES = 128 * 128;
    constexpr int BBYTES = NT * 128;
    constexpr int STAGE  = 2 * ABYTES + 2 * BBYTES;
    constexpr int MI = (NT == 128) ? 4 : 2;
    constexpr int NI = 4;

    const uint32_t sm32 = smem_u32_of(smem);
    const int tid  = threadIdx.x;
    const int wid  = tid >> 5;
    const int lane = tid & 31;

    const int mwarp = (NT == 128) ? ((wid & 1) * 64) : ((wid & 3) * 32);
    const int nwarp = (NT == 128) ? ((wid >> 1) * 32) : ((wid >> 2) * 32);

    const int lchunk = tid & 7;
    const int lrow   = tid >> 3;

    float acc[MI][NI][4];
#pragma unroll
    for (int i = 0; i < MI; i++)
#pragma unroll
        for (int j = 0; j < NI; j++)
#pragma unroll
            for (int r = 0; r < 4; r++) acc[i][j][r] = 0.f;

    auto load_chunk = [&](int c, int s) {
        const uint32_t base = sm32 + s * STAGE;
        const size_t kofs = (size_t)kbase + (size_t)c * 64 + lchunk * 8;
#pragma unroll
        for (int r = 0; r < 128; r += 32) {
            const int row = lrow + r;
            const size_t go = (size_t)(m0 + row) * Kd + kofs;
            const uint32_t so = base + row * 128 + ((lchunk ^ (row & 7)) << 4);
            cp16(so,          Ahi + go);
            cp16(so + ABYTES, Alo + go);
        }
#pragma unroll
        for (int r = 0; r < NT; r += 32) {
            const int row = lrow + r;
            const size_t go = (size_t)(n0 + row) * Kd + kofs;
            const uint32_t so = base + 2 * ABYTES + row * 128 + ((lchunk ^ (row & 7)) << 4);
            cp16(so,          Bhi + go);
            cp16(so + BBYTES, Blo + go);
        }
        CP_COMMIT();
    };

    auto compute_chunk = [&](int s) {
        const uint32_t aBase = sm32 + s * STAGE;
        const uint32_t bBase = aBase + 2 * ABYTES;
#pragma unroll
        for (int ks = 0; ks < 4; ks++) {
            uint32_t aHi[MI][4], aLo[MI][4], bHi[NI][2], bLo[NI][2];
#pragma unroll
            for (int mi = 0; mi < MI; mi++) {
                const int row = mwarp + mi * 16 + (lane & 15);
                const int chunk = ks * 2 + (lane >> 4);
                const uint32_t off = row * 128 + ((chunk ^ (row & 7)) << 4);
                ldm_x4(aHi[mi], aBase + off);
                ldm_x4(aLo[mi], aBase + ABYTES + off);
            }
#pragma unroll
            for (int nj = 0; nj < NI / 2; nj++) {
                const int row = nwarp + nj * 16 + ((lane >> 4) << 3) + (lane & 7);
                const int chunk = ks * 2 + ((lane >> 3) & 1);
                const uint32_t off = row * 128 + ((chunk ^ (row & 7)) << 4);
                uint32_t r4[4];
                ldm_x4(r4, bBase + off);
                bHi[nj * 2][0] = r4[0]; bHi[nj * 2][1] = r4[1];
                bHi[nj * 2 + 1][0] = r4[2]; bHi[nj * 2 + 1][1] = r4[3];
                ldm_x4(r4, bBase + BBYTES + off);
                bLo[nj * 2][0] = r4[0]; bLo[nj * 2][1] = r4[1];
                bLo[nj * 2 + 1][0] = r4[2]; bLo[nj * 2 + 1][1] = r4[3];
            }
#pragma unroll
            for (int mi = 0; mi < MI; mi++)
#pragma unroll
                for (int ni = 0; ni < NI; ni++) {
                    mma_bf16(acc[mi][ni], aHi[mi], bHi[ni]);
                    mma_bf16(acc[mi][ni], aHi[mi], bLo[ni]);
                    mma_bf16(acc[mi][ni], aLo[mi], bHi[ni]);
                }
        }
    };

    load_chunk(0, 0);
    if (nch > 1) load_chunk(1, 1);
    for (int c = 0; c < nch; c++) {
        if (c + 1 < nch) { CP_WAIT1(); } else { CP_WAIT0(); }
        __syncthreads();
        if (c + 2 < nch) load_chunk(c + 2, (c + 2) % 3);
        compute_chunk(c % 3);
    }

#pragma unroll
    for (int mi = 0; mi < MI; mi++)
#pragma unroll
        for (int ni = 0; ni < NI; ni++) {
            const int row = m0 + mwarp + mi * 16 + (lane >> 2);
            const int col = n0 + nwarp + ni * 8 + ((lane & 3) << 1);
            if (EPI == 1) {
                float f0 = acc[mi][ni][0], f1 = acc[mi][ni][1];
                float f2 = acc[mi][ni][2], f3 = acc[mi][ni][3];
                bf16 h0 = __float2bfloat16(f0), h1 = __float2bfloat16(f1);
                bf16 h2 = __float2bfloat16(f2), h3 = __float2bfloat16(f3);
                bf16 l0 = __float2bfloat16(f0 - __bfloat162float(h0));
                bf16 l1 = __float2bfloat16(f1 - __bfloat162float(h1));
                bf16 l2 = __float2bfloat16(f2 - __bfloat162float(h2));
                bf16 l3 = __float2bfloat16(f3 - __bfloat162float(h3));
                *reinterpret_cast<__nv_bfloat162*>(Chi + (size_t)row * Ntot + col) =
                    __halves2bfloat162(h0, h1);
                *reinterpret_cast<__nv_bfloat162*>(Clo + (size_t)row * Ntot + col) =
                    __halves2bfloat162(l0, l1);
                *reinterpret_cast<__nv_bfloat162*>(Chi + (size_t)(row + 8) * Ntot + col) =
                    __halves2bfloat162(h2, h3);
                *reinterpret_cast<__nv_bfloat162*>(Clo + (size_t)(row + 8) * Ntot + col) =
                    __halves2bfloat162(l2, l3);
            } else {
                *reinterpret_cast<float2*>(C + (size_t)row * Ntot + col) =
                    make_float2(acc[mi][ni][0], acc[mi][ni][1]);
                *reinterpret_cast<float2*>(C + (size_t)(row + 8) * Ntot + col) =
                    make_float2(acc[mi][ni][2], acc[mi][ni][3]);
            }
        }
}

// ---------------------------------------------------------------------------
// GEMM wrapper kernels
// ---------------------------------------------------------------------------
__global__ __launch_bounds__(256, 1)
void mm_down_kernel(const bf16* __restrict__ xhi, const bf16* __restrict__ xlo,
                    const bf16* __restrict__ Bqhi, const bf16* __restrict__ Bqlo,
                    const bf16* __restrict__ Bkhi, const bf16* __restrict__ Bklo,
                    bf16* __restrict__ qlhi, bf16* __restrict__ qllo,
                    bf16* __restrict__ ckvhi, bf16* __restrict__ ckvlo)
{
    extern __shared__ __align__(1024) uint8_t smem[];
    const int bx = blockIdx.x;
    const int seg = bx >> 6;
    const int b = bx & 63;
    const int m0 = (b & 15) * 128;
    const int n0 = (b >> 4) * 128;
    if (seg == 0)
        mm_core<128, 1>(xhi, xlo, Bqhi, Bqlo, nullptr, qlhi, qllo,
                        Dn, Ln, m0, n0, 0, 32, smem);
    else
        mm_core<128, 1>(xhi, xlo, Bkhi, Bklo, nullptr, ckvhi, ckvlo,
                        Dn, Ln, m0, n0, 0, 32, smem);
}

__global__ __launch_bounds__(256, 1)
void mm_up_kernel(const bf16* __restrict__ qlhi, const bf16* __restrict__ qllo,
                  const bf16* __restrict__ ckvhi, const bf16* __restrict__ ckvlo,
                  const bf16* __restrict__ Wquhi, const bf16* __restrict__ Wqulo,
                  const bf16* __restrict__ Wqrhi, const bf16* __restrict__ Wqrlo,
                  const bf16* __restrict__ Wkuhi, const bf16* __restrict__ Wkulo,
                  const bf16* __restrict__ Wvuhi, const bf16* __restrict__ Wvulo,
                  float* __restrict__ q, float* __restrict__ qr,
                  float* __restrict__ k, float* __restrict__ v)
{
    extern __shared__ __align__(1024) uint8_t smem[];
    const int bx = blockIdx.x;
    if (bx < 256) {
        mm_core<128, 0>(qlhi, qllo, Wquhi, Wqulo, q, nullptr, nullptr,
                        Ln, Dn, (bx & 15) * 128, (bx >> 4) * 128, 0, 8, smem);
    } else if (bx < 384) {
        const int b = bx - 256;
        mm_core<128, 0>(qlhi, qllo, Wqrhi, Wqrlo, qr, nullptr, nullptr,
                        Ln, Hn * RDn, (b & 15) * 128, (b >> 4) * 128, 0, 8, smem);
    } else if (bx < 640) {
        const int b = bx - 384;
        mm_core<128, 0>(ckvhi, ckvlo, Wkuhi, Wkulo, k, nullptr, nullptr,
                        Ln, Dn, (b & 15) * 128, (b >> 4) * 128, 0, 8, smem);
    } else {
        const int b = bx - 640;
        mm_core<128, 0>(ckvhi, ckvlo, Wvuhi, Wvulo, v, nullptr, nullptr,
                        Ln, Dn, (b & 15) * 128, (b >> 4) * 128, 0, 8, smem);
    }
}

__global__ __launch_bounds__(256, 1)
void mm_kr_kernel(const bf16* __restrict__ xhi, const bf16* __restrict__ xlo,
                  const bf16* __restrict__ Bhi, const bf16* __restrict__ Blo,
                  float* __restrict__ krp)
{
    extern __shared__ __align__(1024) uint8_t smem[];
    const int bx = blockIdx.x;
    const int mt = bx & 15;
    const int ks = bx >> 4;
    mm_core<64, 0>(xhi, xlo, Bhi, Blo, krp + (size_t)ks * Tn * RDn,
                   nullptr, nullptr,
                   Dn, RDn, mt * 128, 0, ks * (Dn / KSPLIT), (Dn / KSPLIT) / 64, smem);
}

__global__ __launch_bounds__(256, 1)
void mm_wo_kernel(const bf16* __restrict__ aohi, const bf16* __restrict__ aolo,
                  const bf16* __restrict__ Bhi, const bf16* __restrict__ Blo,
                  float* __restrict__ out)
{
    extern __shared__ __align__(1024) uint8_t smem[];
    const int bx = blockIdx.x;
    mm_core<128, 0>(aohi, aolo, Bhi, Blo, out, nullptr, nullptr,
                    Dn, Dn, (bx & 15) * 128, (bx >> 4) * 128, 0, 32, smem);
}

// ---------------------------------------------------------------------------
// Merged preprocessing: x split (vectorized) + 8 weight transpose-splits.
// Block = 256 threads.
//   blocks [0, 2048):      x split, 2048 floats per block (float4 IO)
//   blocks [2048, 11904):  tsplit segments, one 32x32 tile per block
// ---------------------------------------------------------------------------
__device__ __forceinline__ void tsplit_tile(
    const float* __restrict__ W, bf16* __restrict__ hi, bf16* __restrict__ lo,
    int Kd, int N, int bx, int by)
{
    __shared__ float tile[32][33];
    const int n0 = bx * 32, k0 = by * 32;
    const int tx = threadIdx.x & 31;
    const int ty = threadIdx.x >> 5;
#pragma unroll
    for (int i = 0; i < 32; i += 8)
        tile[ty + i][tx] = W[(size_t)(k0 + ty + i) * N + n0 + tx];
    __syncthreads();
#pragma unroll
    for (int i = 0; i < 32; i += 8) {
        float f = tile[tx][ty + i];
        bf16 h = __float2bfloat16(f);
        size_t o = (size_t)(n0 + ty + i) * Kd + k0 + tx;
        hi[o] = h;
        lo[o] = __float2bfloat16(f - __bfloat162float(h));
    }
}

__global__ __launch_bounds__(256)
void prep_kernel(const float* __restrict__ x,
                 const float* __restrict__ Wqd,  const float* __restrict__ Wqu,
                 const float* __restrict__ Wqr,  const float* __restrict__ Wkvd,
                 const float* __restrict__ Wku,  const float* __restrict__ Wvu,
                 const float* __restrict__ Wkr,  const float* __restrict__ Wo,
                 bf16* __restrict__ xhi, bf16* __restrict__ xlo,
                 bf16* __restrict__ WqdThi,  bf16* __restrict__ WqdTlo,
                 bf16* __restrict__ WkvdThi, bf16* __restrict__ WkvdTlo,
                 bf16* __restrict__ WquThi,  bf16* __restrict__ WquTlo,
                 bf16* __restrict__ WqrThi,  bf16* __restrict__ WqrTlo,
                 bf16* __restrict__ WkuThi,  bf16* __restrict__ WkuTlo,
                 bf16* __restrict__ WvuThi,  bf16* __restrict__ WvuTlo,
                 bf16* __restrict__ WkrThi,  bf16* __restrict__ WkrTlo,
                 bf16* __restrict__ WoThi,   bf16* __restrict__ WoTlo)
{
    const int b = blockIdx.x;
    if (b < 2048) {
        // x split: 2048 floats per block, float4 in, 4xbf16 (uint2) out
        const int base = b * 2048 + threadIdx.x * 4;
#pragma unroll
        for (int rep = 0; rep < 2; rep++) {
            const int i = base + rep * 1024;
            float4 f = *reinterpret_cast<const float4*>(x + i);
            bf16 h0 = __float2bfloat16(f.x), h1 = __float2bfloat16(f.y);
            bf16 h2 = __float2bfloat16(f.z), h3 = __float2bfloat16(f.w);
            __nv_bfloat162 hA = __halves2bfloat162(h0, h1);
            __nv_bfloat162 hB = __halves2bfloat162(h2, h3);
            __nv_bfloat162 lA = __halves2bfloat162(
                __float2bfloat16(f.x - __bfloat162float(h0)),
                __float2bfloat16(f.y - __bfloat162float(h1)));
            __nv_bfloat162 lB = __halves2bfloat162(
                __float2bfloat16(f.z - __bfloat162float(h2)),
                __float2bfloat16(f.w - __bfloat162float(h3)));
            *reinterpret_cast<__nv_bfloat162*>(xhi + i)     = hA;
            *reinterpret_cast<__nv_bfloat162*>(xhi + i + 2) = hB;
            *reinterpret_cast<__nv_bfloat162*>(xlo + i)     = lA;
            *reinterpret_cast<__nv_bfloat162*>(xlo + i + 2) = lB;
        }
        return;
    }
    int rb = b - 2048;
    if (rb < 1024)      { tsplit_tile(Wqd,  WqdThi,  WqdTlo,  Dn, Ln,      rb & 15, rb >> 4); return; }
    rb -= 1024;
    if (rb < 1024)      { tsplit_tile(Wkvd, WkvdThi, WkvdTlo, Dn, Ln,      rb & 15, rb >> 4); return; }
    rb -= 1024;
    if (rb < 1024)      { tsplit_tile(Wqu,  WquThi,  WquTlo,  Ln, Dn,      rb & 63, rb >> 6); return; }
    rb -= 1024;
    if (rb < 512)       { tsplit_tile(Wqr,  WqrThi,  WqrTlo,  Ln, Hn*RDn,  rb & 31, rb >> 5); return; }
    rb -= 512;
    if (rb < 1024)      { tsplit_tile(Wku,  WkuThi,  WkuTlo,  Ln, Dn,      rb & 63, rb >> 6); return; }
    rb -= 1024;
    if (rb < 1024)      { tsplit_tile(Wvu,  WvuThi,  WvuTlo,  Ln, Dn,      rb & 63, rb >> 6); return; }
    rb -= 1024;
    if (rb < 128)       { tsplit_tile(Wkr,  WkrThi,  WkrTlo,  Dn, RDn,     rb & 1,  rb >> 1); return; }
    rb -= 128;
    /* Wo: 4096 */      { tsplit_tile(Wo,   WoThi,   WoTlo,   Dn, Dn,      rb & 63, rb >> 6); }
}

// ---------------------------------------------------------------------------
// Merged RoPE: qr in-place + kr split-K reduce + rope
// ---------------------------------------------------------------------------
__global__ void rope_kernel(float* __restrict__ qr,
                            const float* __restrict__ krp,
                            float* __restrict__ kr)
{
    int i = blockIdx.x * blockDim.x + threadIdx.x;
    if (i < Tn * Hn * 32) {
        int r = i & 31;
        int h = (i >> 5) & (Hn - 1);
        int t = i >> 9;
        float f = powf(10000.0f, -(float)r / 32.0f);
        float ang = (float)t * f;
        float c = cosf(ang), s = sinf(ang);
        int base = t * (Hn * RDn) + h * RDn + r;
        float a = qr[base];
        float bv = qr[base + 32];
        qr[base]      = a * c - bv * s;
        qr[base + 32] = bv * c + a * s;
        return;
    }
    i -= Tn * Hn * 32;
    if (i >= Tn * 32) return;
    int r = i & 31;
    int t = i >> 5;
    float a = 0.f, bv = 0.f;
#pragma unroll
    for (int s = 0; s < KSPLIT; s++) {
        a  += krp[(size_t)s * Tn * RDn + t * RDn + r];
        bv += krp[(size_t)s * Tn * RDn + t * RDn + r + 32];
    }
    float f = powf(10000.0f, -(float)r / 32.0f);
    float ang = (float)t * f;
    float c = cosf(ang), sn = sinf(ang);
    kr[t * RDn + r]      = a * c - bv * sn;
    kr[t * RDn + r + 32] = bv * c + a * sn;
}

// ---------------------------------------------------------------------------
// Sparse top-k attention, v2: cooperative row gather (full sector efficiency).
// One warp per (t, h). For each selected token j, ALL lanes cooperatively
// load contiguous 512B of K row + 256B of kr row, partial-dot, warp-reduce.
// ---------------------------------------------------------------------------
__global__ void attn_kernel(const float* __restrict__ q,
                            const float* __restrict__ qr,
                            const float* __restrict__ kmat,
                            const float* __restrict__ vmat,
                            const float* __restrict__ kr,
                            const int*   __restrict__ topk,
                            bf16* __restrict__ aohi, bf16* __restrict__ aolo)
{
    const int warp = (blockIdx.x * blockDim.x + threadIdx.x) >> 5;
    const int lane = threadIdx.x & 31;
    if (warp >= Tn * Hn) return;
    const int t = warp >> 4;
    const int h = warp & (Hn - 1);

    const int idx = topk[t * Kn + lane];

    // my slice of q (4 elems) and qr (2 elems) — reused across all j
    const float4 qv = *reinterpret_cast<const float4*>(
        q + (size_t)t * Dn + h * HDn + lane * 4);
    const float2 qrv = *reinterpret_cast<const float2*>(
        qr + (size_t)t * (Hn * RDn) + h * RDn + lane * 2);

    float s = 0.f;
#pragma unroll
    for (int j = 0; j < Kn; j++) {
        const int ij = __shfl_sync(0xFFFFFFFFu, idx, j);
        const float4 kv = *reinterpret_cast<const float4*>(
            kmat + (size_t)ij * Dn + h * HDn + lane * 4);
        const float2 krv = *reinterpret_cast<const float2*>(
            kr + (size_t)ij * RDn + lane * 2);
        float p = qv.x * kv.x + qv.y * kv.y + qv.z * kv.z + qv.w * kv.w
                + qrv.x * krv.x + qrv.y * krv.y;
#pragma unroll
        for (int o = 16; o; o >>= 1) p += __shfl_xor_sync(0xFFFFFFFFu, p, o);
        if (lane == j) s = p;
    }
    s *= SCALE_ATTN;

    // warp softmax over the 32 per-lane scores
    float m = s;
#pragma unroll
    for (int o = 16; o; o >>= 1) m = fmaxf(m, __shfl_xor_sync(0xFFFFFFFFu, m, o));
    float e = expf(s - m);
    float sum = e;
#pragma unroll
    for (int o = 16; o; o >>= 1) sum += __shfl_xor_sync(0xFFFFFFFFu, sum, o);
    float w = e / sum;

    // weighted V sum (fp32, coalesced)
    float acc0 = 0.f, acc1 = 0.f, acc2 = 0.f, acc3 = 0.f;
#pragma unroll
    for (int j = 0; j < Kn; j++) {
        float wj = __shfl_sync(0xFFFFFFFFu, w, j);
        int   ij = __shfl_sync(0xFFFFFFFFu, idx, j);
        const float* vp = vmat + (size_t)ij * Dn + h * HDn;
        acc0 = fmaf(wj, vp[lane],      acc0);
        acc1 = fmaf(wj, vp[lane + 32], acc1);
        acc2 = fmaf(wj, vp[lane + 64], acc2);
        acc3 = fmaf(wj, vp[lane + 96], acc3);
    }
    const size_t opofs = (size_t)t * Dn + h * HDn;
    {
        bf16 h0 = __float2bfloat16(acc0);
        bf16 h1 = __float2bfloat16(acc1);
        bf16 h2 = __float2bfloat16(acc2);
        bf16 h3 = __float2bfloat16(acc3);
        aohi[opofs + lane]      = h0;
        aohi[opofs + lane + 32] = h1;
        aohi[opofs + lane + 64] = h2;
        aohi[opofs + lane + 96] = h3;
        aolo[opofs + lane]      = __float2bfloat16(acc0 - __bfloat162float(h0));
        aolo[opofs + lane + 32] = __float2bfloat16(acc1 - __bfloat162float(h1));
        aolo[opofs + lane + 64] = __float2bfloat16(acc2 - __bfloat162float(h2));
        aolo[opofs + lane + 96] = __float2bfloat16(acc3 - __bfloat162float(h3));
    }
}

// ---------------------------------------------------------------------------
// Launcher
// ---------------------------------------------------------------------------
extern "C" void kernel_launch(void* const* d_in, const int* in_sizes, int n_in,
                              void* d_out, int out_size)
{
    const float* x    = (const float*)d_in[0];
    const float* Wqd  = (const float*)d_in[1];
    const float* Wqu  = (const float*)d_in[2];
    const float* Wqr  = (const float*)d_in[3];
    const float* Wkvd = (const float*)d_in[4];
    const float* Wku  = (const float*)d_in[5];
    const float* Wvu  = (const float*)d_in[6];
    const float* Wkr  = (const float*)d_in[7];
    const float* Wo   = (const float*)d_in[8];
    const int*   topk = (const int*)  d_in[9];
    float* out = (float*)d_out;

    float *q, *qr, *k, *v, *kr, *krp;
    cudaGetSymbolAddress((void**)&q,   g_q);
    cudaGetSymbolAddress((void**)&qr,  g_qr);
    cudaGetSymbolAddress((void**)&k,   g_k);
    cudaGetSymbolAddress((void**)&v,   g_v);
    cudaGetSymbolAddress((void**)&kr,  g_kr);
    cudaGetSymbolAddress((void**)&krp, g_krp);

    bf16 *x_hi, *x_lo, *ql_hi, *ql_lo, *ckv_hi, *ckv_lo, *ao_hi, *ao_lo;
    cudaGetSymbolAddress((void**)&x_hi,   g_x_hi);
    cudaGetSymbolAddress((void**)&x_lo,   g_x_lo);
    cudaGetSymbolAddress((void**)&ql_hi,  g_ql_hi);
    cudaGetSymbolAddress((void**)&ql_lo,  g_ql_lo);
    cudaGetSymbolAddress((void**)&ckv_hi, g_ckv_hi);
    cudaGetSymbolAddress((void**)&ckv_lo, g_ckv_lo);
    cudaGetSymbolAddress((void**)&ao_hi,  g_ao_hi);
    cudaGetSymbolAddress((void**)&ao_lo,  g_ao_lo);

    bf16 *WqdT_hi, *WqdT_lo, *WkvdT_hi, *WkvdT_lo, *WquT_hi, *WquT_lo,
         *WqrT_hi, *WqrT_lo, *WkuT_hi, *WkuT_lo, *WvuT_hi, *WvuT_lo,
         *WkrT_hi, *WkrT_lo, *WoT_hi, *WoT_lo;
    cudaGetSymbolAddress((void**)&WqdT_hi,  g_WqdT_hi);
    cudaGetSymbolAddress((void**)&WqdT_lo,  g_WqdT_lo);
    cudaGetSymbolAddress((void**)&WkvdT_hi, g_WkvdT_hi);
    cudaGetSymbolAddress((void**)&WkvdT_lo, g_WkvdT_lo);
    cudaGetSymbolAddress((void**)&WquT_hi,  g_WquT_hi);
    cudaGetSymbolAddress((void**)&WquT_lo,  g_WquT_lo);
    cudaGetSymbolAddress((void**)&WqrT_hi,  g_WqrT_hi);
    cudaGetSymbolAddress((void**)&WqrT_lo,  g_WqrT_lo);
    cudaGetSymbolAddress((void**)&WkuT_hi,  g_WkuT_hi);
    cudaGetSymbolAddress((void**)&WkuT_lo,  g_WkuT_lo);
    cudaGetSymbolAddress((void**)&WvuT_hi,  g_WvuT_hi);
    cudaGetSymbolAddress((void**)&WvuT_lo,  g_WvuT_lo);
    cudaGetSymbolAddress((void**)&WkrT_hi,  g_WkrT_hi);
    cudaGetSymbolAddress((void**)&WkrT_lo,  g_WkrT_lo);
    cudaGetSymbolAddress((void**)&WoT_hi,   g_WoT_hi);
    cudaGetSymbolAddress((void**)&WoT_lo,   g_WoT_lo);

    const int SMEM_128 = 196608;   // 3 stages x 64KB
    const int SMEM_64  = 147456;   // 3 stages x 48KB
    cudaFuncSetAttribute(mm_down_kernel, cudaFuncAttributeMaxDynamicSharedMemorySize, SMEM_128);
    cudaFuncSetAttribute(mm_up_kernel,   cudaFuncAttributeMaxDynamicSharedMemorySize, SMEM_128);
    cudaFuncSetAttribute(mm_wo_kernel,   cudaFuncAttributeMaxDynamicSharedMemorySize, SMEM_128);
    cudaFuncSetAttribute(mm_kr_kernel,   cudaFuncAttributeMaxDynamicSharedMemorySize, SMEM_64);

    // 1) merged preprocessing (x split + all weight transpose-splits)
    prep_kernel<<<11904, 256>>>(x, Wqd, Wqu, Wqr, Wkvd, Wku, Wvu, Wkr, Wo,
                                x_hi, x_lo,
                                WqdT_hi, WqdT_lo, WkvdT_hi, WkvdT_lo,
                                WquT_hi, WquT_lo, WqrT_hi, WqrT_lo,
                                WkuT_hi, WkuT_lo, WvuT_hi, WvuT_lo,
                                WkrT_hi, WkrT_lo, WoT_hi, WoT_lo);

    // 2) kr partials (split-K x 8)
    mm_kr_kernel<<<16 * KSPLIT, 256, SMEM_64>>>(x_hi, x_lo, WkrT_hi, WkrT_lo, krp);

    // 3) down-projections (merged)
    mm_down_kernel<<<128, 256, SMEM_128>>>(x_hi, x_lo,
                                           WqdT_hi, WqdT_lo, WkvdT_hi, WkvdT_lo,
                                           ql_hi, ql_lo, ckv_hi, ckv_lo);

    // 4) up-projections (merged: q, qr, k, v)
    mm_up_kernel<<<896, 256, SMEM_128>>>(ql_hi, ql_lo, ckv_hi, ckv_lo,
                                         WquT_hi, WquT_lo, WqrT_hi, WqrT_lo,
                                         WkuT_hi, WkuT_lo, WvuT_hi, WvuT_lo,
                                         q, qr, k, v);

    // 5) merged rope (qr in-place + kr reduce)
    rope_kernel<<<(Tn * Hn * 32 + Tn * 32 + 255) / 256, 256>>>(qr, krp, kr);

    // 6) sparse attention (cooperative gather, emits bf16 hi/lo ao)
    attn_kernel<<<(Tn * Hn * 32 + 255) / 256, 256>>>(q, qr, k, v, kr, topk, ao_hi, ao_lo);

    // 7) output projection
    mm_wo_kernel<<<256, 256, SMEM_128>>>(ao_hi, ao_lo, WoT_hi, WoT_lo, out);
}